// round 10
// baseline (speedup 1.0000x reference)
#include <cuda_runtime.h>
#include <cuda_fp16.h>
#include <cstdint>
#include <math.h>

// ---------------- problem constants ----------------
#define BB 32
#define TT 2048
#define CC 512          // E == F == 512
#define NN 65536        // B*T
#define HH 8
#define EPS 1e-5

// ---------------- scratch (device globals; allocation-free rule) ----------
__device__ float gX[33554432];     // state, layout (C, B, T) fp32
__device__ __half gBt[33554432];   // GEMM B operand, n-major [65536][512] fp16
__device__ __half gST[33554432];   // K-major fp16 staging [512][65536]
__device__ __half gQKV[100663296]; // merged QKV output fp16 [1536][65536]
__device__ __half gWb[262144];     // pw1 weights fp16
__device__ __half gWb2[262144];    // pw2 weights fp16
__device__ __half gWp[262144];     // wp weights fp16
__device__ __half gWff[262144];    // ff weights fp16
__device__ __half gWqkv[786432];   // merged q|k|v weights fp16 [1536][512]
__device__ float gBqkv[1536];      // merged q|k|v bias

__device__ float g_bacc[64];       // per-batch (sum, sumsq) fp32 accumulators
__device__ float g_bmean[32], g_brstd[32];
__device__ float g_tacc[4096];     // per-t (sum, sumsq)
__device__ float g_tmean[2048], g_trstd[2048];

// ================= helpers =================
__device__ __forceinline__ uint32_t smem_u32(const void* p) {
    uint32_t a;
    asm("{ .reg .u64 t; cvta.to.shared.u64 t, %1; cvt.u32.u64 %0, t; }" : "=r"(a) : "l"(p));
    return a;
}
__device__ __forceinline__ void cp_async16(uint32_t smaddr, const void* g) {
    asm volatile("cp.async.cg.shared.global [%0], [%1], 16;" :: "r"(smaddr), "l"(g));
}
#define CP_COMMIT() asm volatile("cp.async.commit_group;" ::: "memory")
#define CP_WAIT1()  asm volatile("cp.async.wait_group 1;" ::: "memory")

__device__ __forceinline__ void ldmatrix_x4(uint32_t& r0, uint32_t& r1, uint32_t& r2,
                                            uint32_t& r3, uint32_t addr) {
    asm volatile("ldmatrix.sync.aligned.m8n8.x4.shared.b16 {%0,%1,%2,%3}, [%4];"
        : "=r"(r0), "=r"(r1), "=r"(r2), "=r"(r3) : "r"(addr));
}
__device__ __forceinline__ void mma16816(float* d, const uint32_t* a, uint32_t b0, uint32_t b1) {
    asm volatile(
        "mma.sync.aligned.m16n8k16.row.col.f32.f16.f16.f32 "
        "{%0,%1,%2,%3}, {%4,%5,%6,%7}, {%8,%9}, {%0,%1,%2,%3};"
        : "+f"(d[0]), "+f"(d[1]), "+f"(d[2]), "+f"(d[3])
        : "r"(a[0]), "r"(a[1]), "r"(a[2]), "r"(a[3]), "r"(b0), "r"(b1));
}

// ---------------- all weight converts + qkv pack in ONE kernel -------------
__global__ void k_cvtall(const float* __restrict__ pw1, const float* __restrict__ pw2,
                         const float* __restrict__ wp, const float* __restrict__ ffw,
                         const float* __restrict__ wq, const float* __restrict__ wk,
                         const float* __restrict__ wv, const float* __restrict__ bq,
                         const float* __restrict__ bk, const float* __restrict__ bv,
                         __half* __restrict__ W1, __half* __restrict__ W2,
                         __half* __restrict__ Wp, __half* __restrict__ Wff,
                         __half* __restrict__ Wqkv, float* __restrict__ Bqkv) {
    int idx = blockIdx.x * 256 + threadIdx.x;
    if (idx < 262144) {
        W1[idx] = __float2half_rn(pw1[idx]);
    } else if (idx < 524288) {
        int o = idx - 262144; W2[o] = __float2half_rn(pw2[o]);
    } else if (idx < 786432) {
        int o = idx - 524288; Wp[o] = __float2half_rn(wp[o]);
    } else if (idx < 1048576) {
        int o = idx - 786432; Wff[o] = __float2half_rn(ffw[o]);
    } else {
        int o2 = idx - 1048576;           // 0..786431
        int sel = o2 >> 18;
        int off = o2 & 262143;
        const float* src = (sel == 0) ? wq : ((sel == 1) ? wk : wv);
        Wqkv[o2] = __float2half_rn(src[off]);
        if (off < 512) {
            const float* bs = (sel == 0) ? bq : ((sel == 1) ? bk : bv);
            Bqkv[sel * 512 + off] = bs[off];
        }
    }
}

// ---------------- input transpose + positional encoding + batch stats ------
__global__ void k_transpose_in(const float* __restrict__ in, float* __restrict__ X) {
    __shared__ float tile[32][33];
    __shared__ float rs[256], rq[256];
    int b = blockIdx.z;
    int t0 = blockIdx.x * 32, c0 = blockIdx.y * 32;
    int tx = threadIdx.x, ty = threadIdx.y;
    #pragma unroll
    for (int i = ty; i < 32; i += 8)
        tile[i][tx] = in[((size_t)b * TT + t0 + i) * CC + c0 + tx];
    __syncthreads();
    float s = 0.0f, q = 0.0f;
    #pragma unroll
    for (int i = ty; i < 32; i += 8) {
        int c = c0 + i;
        float div = expf((float)(c & ~1) * (-9.210340371976184f / 512.0f));
        float ang = (float)b * div;
        float pe = (c & 1) ? cosf(ang) : sinf(ang);
        float v = tile[tx][i] + pe;
        X[((size_t)c * BB + b) * TT + t0 + tx] = v;
        s += v; q += v * v;
    }
    int tid = ty * 32 + tx;
    rs[tid] = s; rq[tid] = q;
    __syncthreads();
    for (int o = 128; o > 0; o >>= 1) {
        if (tid < o) { rs[tid] += rs[tid + o]; rq[tid] += rq[tid + o]; }
        __syncthreads();
    }
    if (tid == 0) {
        atomicAdd(&g_bacc[2 * b], rs[0]);
        atomicAdd(&g_bacc[2 * b + 1], rq[0]);
    }
}

// ---------------- finalize per-batch stats (and re-zero accumulators) ------
__global__ void k_bfinal() {
    int b = threadIdx.x;
    if (b < 32) {
        double s = (double)g_bacc[2 * b], q = (double)g_bacc[2 * b + 1];
        double n = 1048576.0;
        double mu = s / n;
        double var = q / n - mu * mu;
        g_bmean[b] = (float)mu;
        g_brstd[b] = (float)(1.0 / sqrt(var + (double)EPS));
        g_bacc[2 * b] = 0.0f;
        g_bacc[2 * b + 1] = 0.0f;
    }
}

// ---------------- finalize per-t stats ----------------
__global__ void k_tfinal() {
    int t = blockIdx.x * 256 + threadIdx.x;
    double s = (double)g_tacc[2 * t], q = (double)g_tacc[2 * t + 1];
    double n = 16384.0;
    double mu = s / n;
    double var = q / n - mu * mu;
    g_tmean[t] = (float)mu;
    g_trstd[t] = (float)(1.0 / sqrt(var + (double)EPS));
    g_tacc[2 * t] = 0.0f;
    g_tacc[2 * t + 1] = 0.0f;
}

// ---------------- fused per-batch-LN + depthwise conv (k=7) -> fp16 K-major
__global__ void k_dwconv(const float* __restrict__ X, const float* __restrict__ dww,
                         const float* __restrict__ dwb, __half* __restrict__ D) {
    int c = blockIdx.x, b = blockIdx.y;
    int tid = threadIdx.x;
    __shared__ float s[TT + 16];   // x[t] at s[t+4]
    float mu = g_bmean[b], r = g_brstd[b];
    const float4* row4 = (const float4*)(X + ((size_t)c * BB + b) * TT);
    #pragma unroll
    for (int i = 0; i < 2; i++) {
        int t4 = tid + i * 256;
        float4 v = row4[t4];
        v.x = (v.x - mu) * r; v.y = (v.y - mu) * r;
        v.z = (v.z - mu) * r; v.w = (v.w - mu) * r;
        *(float4*)&s[4 + t4 * 4] = v;
    }
    if (tid < 4) s[tid] = 0.0f;
    else if (tid < 8) s[2048 + tid] = 0.0f;
    __syncthreads();
    float w0 = dww[c * 7 + 0], w1 = dww[c * 7 + 1], w2 = dww[c * 7 + 2], w3 = dww[c * 7 + 3];
    float w4 = dww[c * 7 + 4], w5 = dww[c * 7 + 5], w6 = dww[c * 7 + 6];
    float bias = dwb[c];
    int t0 = tid * 8;
    float xv[16];
    *(float4*)&xv[0]  = *(const float4*)&s[t0];
    *(float4*)&xv[4]  = *(const float4*)&s[t0 + 4];
    *(float4*)&xv[8]  = *(const float4*)&s[t0 + 8];
    *(float4*)&xv[12] = *(const float4*)&s[t0 + 12];
    __half2 oh[4];
    #pragma unroll
    for (int j = 0; j < 8; j += 2) {
        float a0 = bias, a1 = bias;
        a0 += w0 * xv[j + 1]; a1 += w0 * xv[j + 2];
        a0 += w1 * xv[j + 2]; a1 += w1 * xv[j + 3];
        a0 += w2 * xv[j + 3]; a1 += w2 * xv[j + 4];
        a0 += w3 * xv[j + 4]; a1 += w3 * xv[j + 5];
        a0 += w4 * xv[j + 5]; a1 += w4 * xv[j + 6];
        a0 += w5 * xv[j + 6]; a1 += w5 * xv[j + 7];
        a0 += w6 * xv[j + 7]; a1 += w6 * xv[j + 8];
        oh[j >> 1] = __halves2half2(__float2half_rn(a0), __float2half_rn(a1));
    }
    uint4 wv = { *(uint32_t*)&oh[0], *(uint32_t*)&oh[1], *(uint32_t*)&oh[2], *(uint32_t*)&oh[3] };
    *(uint4*)(D + ((size_t)c * BB + b) * TT + t0) = wv;
}

// ---------------- fp16 transpose [512][65536] K-major -> [65536][512] n-major
__global__ void k_tr16(const __half* __restrict__ S, __half* __restrict__ D) {
    __shared__ __half sm[64][72];
    int n0 = blockIdx.x * 64, k0 = blockIdx.y * 64;
    int tid = threadIdx.x;          // 256 threads
    int r = tid >> 2, seg = tid & 3;
    const __half* src = S + (size_t)(k0 + r) * NN + n0 + seg * 16;
    uint4 v0 = *(const uint4*)src;
    uint4 v1 = *(const uint4*)(src + 8);
    const __half* h0 = (const __half*)&v0;
    const __half* h1 = (const __half*)&v1;
    #pragma unroll
    for (int j = 0; j < 8; j++) sm[seg * 16 + j][r] = h0[j];
    #pragma unroll
    for (int j = 0; j < 8; j++) sm[seg * 16 + 8 + j][r] = h1[j];
    __syncthreads();
    int nl = tid >> 2, part = tid & 3;
    uint4 w0 = *(const uint4*)&sm[nl][part * 16];
    uint4 w1 = *(const uint4*)&sm[nl][part * 16 + 8];
    __half* dst = D + (size_t)(n0 + nl) * 512 + k0 + part * 16;
    *(uint4*)dst = w0;
    *(uint4*)(dst + 8) = w1;
}

// ---------------- transposing LN convert: fp32 [512][65536] -> fp16 [65536][512]
// MODE 1: per-batch LN; MODE 2: per-t LN
template <int MODE>
__global__ void k_cvtBt(const float* __restrict__ X, __half* __restrict__ Bt) {
    __shared__ float tile[32][33];
    int n0 = blockIdx.x * 32, k0 = blockIdx.y * 32;
    int tx = threadIdx.x, ty = threadIdx.y;
    int n = n0 + tx;
    float mu, sc;
    if (MODE == 1) { int b = n >> 11; mu = g_bmean[b]; sc = g_brstd[b]; }
    else           { int t = n & (TT - 1); mu = g_tmean[t]; sc = g_trstd[t]; }
    #pragma unroll
    for (int i = ty; i < 32; i += 8)
        tile[i][tx] = (X[(size_t)(k0 + i) * NN + n] - mu) * sc;
    __syncthreads();
    #pragma unroll
    for (int i = ty; i < 32; i += 8)
        Bt[(size_t)(n0 + i) * 512 + k0 + tx] = __float2half_rn(tile[tx][i]);
}

// ---------------- tensor-core GEMM: C[M,65536] (+)= W @ X + bias ------------
// A fp16 [M][512] row-major; B fp16 [65536][512] n-major (k contiguous).
// CTA 128x128, 8 warps (warp 64x32), K chunks of 64, 3-stage cp.async.
// Both operands use normal (non-trans) ldmatrix — round-4 verified mapping.
#define KSTAGE 64
#define NSTG 3
#define A_BYTES 16384
#define STG_BYTES 32768
#define MMA_SMEM (NSTG * STG_BYTES)
#define NKC 8

template <int BETA, int STATS, int TRANS, typename OutT>
__global__ void __launch_bounds__(256, 2)
k_mma(const __half* __restrict__ Wb, const __half* __restrict__ Bt,
      const float* __restrict__ bias, OutT* __restrict__ C, const float* __restrict__ Cin) {
    extern __shared__ char dsm[];
    uint32_t smb = smem_u32(dsm);
    int tid = threadIdx.x;
    int wid = tid >> 5, lane = tid & 31;
    int m0 = blockIdx.x * 128, n0 = blockIdx.y * 128;
    int warp_m = wid >> 2, warp_n = wid & 3;

    float acc[4][4][4];
    #pragma unroll
    for (int a = 0; a < 4; a++)
        #pragma unroll
        for (int b = 0; b < 4; b++)
            #pragma unroll
            for (int c = 0; c < 4; c++) acc[a][b][c] = 0.0f;

    int arow = tid >> 3, ach = tid & 7;

    auto prefetch = [&](int st, int kc) {
        uint32_t sA = smb + st * STG_BYTES;
        uint32_t sB = sA + A_BYTES;
        #pragma unroll
        for (int i = 0; i < 4; i++) {
            int row = arow + i * 32;
            uint32_t sw = (uint32_t)(row * 128 + ((ach ^ (row & 7)) << 4));
            cp_async16(sA + sw, Wb + (size_t)(m0 + row) * 512 + kc * KSTAGE + ach * 8);
            cp_async16(sB + sw, Bt + (size_t)(n0 + row) * 512 + kc * KSTAGE + ach * 8);
        }
    };

    prefetch(0, 0); CP_COMMIT();
    prefetch(1, 1); CP_COMMIT();

    int lr = lane & 7, lq = lane >> 3;
    int rowoff = lr + (lq & 1) * 8;
    int csel = lq >> 1;

    for (int i = 0; i < NKC; i++) {
        CP_WAIT1();
        __syncthreads();
        if (i + 2 < NKC) prefetch((i + 2) % NSTG, i + 2);
        CP_COMMIT();

        uint32_t sA = smb + (i % NSTG) * STG_BYTES;
        uint32_t sB = sA + A_BYTES;
        #pragma unroll
        for (int kk = 0; kk < 4; kk++) {
            int chnk = kk * 2 + csel;
            uint32_t bf[2][4];
            #pragma unroll
            for (int nf = 0; nf < 2; nf++) {
                int row = warp_n * 32 + nf * 16 + rowoff;
                ldmatrix_x4(bf[nf][0], bf[nf][1], bf[nf][2], bf[nf][3],
                            sB + row * 128 + ((chnk ^ (row & 7)) << 4));
            }
            uint32_t af[4][4];
            #pragma unroll
            for (int mf = 0; mf < 4; mf++) {
                int row = warp_m * 64 + mf * 16 + rowoff;
                ldmatrix_x4(af[mf][0], af[mf][1], af[mf][2], af[mf][3],
                            sA + row * 128 + ((chnk ^ (row & 7)) << 4));
            }
            #pragma unroll
            for (int mf = 0; mf < 4; mf++)
                #pragma unroll
                for (int t = 0; t < 4; t++)
                    mma16816(acc[mf][t], af[mf], bf[t >> 1][t & 1], bf[t >> 1][(t & 1) + 2]);
        }
        // no trailing sync: leading sync of next iter protects stage reuse
    }
    __syncthreads();   // all mainloop SMEM reads done before epilogue reuses dsm

    // ---- epilogue ----
    float* colsum = (float*)dsm;        // STATS==2: [128] + [128]
    float* colsq  = colsum + 128;
    float* stg    = (float*)dsm;        // TRANS: [128][132]
    if (STATS == 2) {
        if (tid < 128) { colsum[tid] = 0.0f; colsq[tid] = 0.0f; }
        __syncthreads();
    }
    float s_part = 0.0f, q_part = 0.0f;
    int g = lane >> 2, tg = lane & 3;
    #pragma unroll
    for (int mf = 0; mf < 4; mf++) {
        int mlA = warp_m * 64 + mf * 16 + g;
        int mlB = mlA + 8;
        int mA = m0 + mlA, mB2 = m0 + mlB;
        float bva = bias[mA], bvb = bias[mB2];
        #pragma unroll
        for (int t = 0; t < 4; t++) {
            int nl = warp_n * 32 + t * 8 + tg * 2;
            int n = n0 + nl;
            size_t o0 = (size_t)mA * NN + n;
            size_t o1 = (size_t)mB2 * NN + n;
            float v00 = acc[mf][t][0] + bva, v01 = acc[mf][t][1] + bva;
            float v10 = acc[mf][t][2] + bvb, v11 = acc[mf][t][3] + bvb;
            if (BETA) {
                float2 p0 = *(const float2*)&Cin[o0];
                float2 p1 = *(const float2*)&Cin[o1];
                v00 += p0.x; v01 += p0.y;
                v10 += p1.x; v11 += p1.y;
            }
            if (STATS == 1) {
                s_part += v00 + v01 + v10 + v11;
                q_part += v00 * v00 + v01 * v01 + v10 * v10 + v11 * v11;
            }
            if (STATS == 2) {
                atomicAdd(&colsum[nl], v00 + v10);
                atomicAdd(&colsum[nl + 1], v01 + v11);
                atomicAdd(&colsq[nl], v00 * v00 + v10 * v10);
                atomicAdd(&colsq[nl + 1], v01 * v01 + v11 * v11);
            }
            if (TRANS) {
                stg[nl * 132 + mlA] = v00;
                stg[(nl + 1) * 132 + mlA] = v01;
                stg[nl * 132 + mlB] = v10;
                stg[(nl + 1) * 132 + mlB] = v11;
            } else if (sizeof(OutT) == 4) {
                float2 w0 = { v00, v01 }, w1 = { v10, v11 };
                *(float2*)&((float*)C)[o0] = w0;
                *(float2*)&((float*)C)[o1] = w1;
            } else {
                __half2 h0 = __halves2half2(__float2half_rn(v00), __float2half_rn(v01));
                __half2 h1 = __halves2half2(__float2half_rn(v10), __float2half_rn(v11));
                *(uint32_t*)&((__half*)C)[o0] = *(uint32_t*)&h0;
                *(uint32_t*)&((__half*)C)[o1] = *(uint32_t*)&h1;
            }
        }
    }
    if (STATS == 1) {
        float* red = (float*)dsm;
        red[tid] = s_part; red[256 + tid] = q_part;
        __syncthreads();
        for (int o = 128; o > 0; o >>= 1) {
            if (tid < o) { red[tid] += red[tid + o]; red[256 + tid] += red[256 + tid + o]; }
            __syncthreads();
        }
        if (tid == 0) {
            int b = n0 >> 11;
            atomicAdd(&g_bacc[2 * b], red[0]);
            atomicAdd(&g_bacc[2 * b + 1], red[256]);
        }
    }
    if (STATS == 2) {
        __syncthreads();
        if (tid < 128) {
            int t = (n0 + tid) & (TT - 1);
            atomicAdd(&g_tacc[2 * t], colsum[tid]);
            atomicAdd(&g_tacc[2 * t + 1], colsq[tid]);
        }
    }
    if (TRANS) {
        __syncthreads();
        int ml = tid & 127;
        for (int nl = tid >> 7; nl < 128; nl += 2)
            ((float*)C)[(size_t)(n0 + nl) * CC + m0 + ml] = stg[nl * 132 + ml];
    }
}

// ---------------- attention over the batch axis (fp16 QKV in, fp16 K-major out)
#define AT 8
#define SQ_OFF 0
#define SK_OFF 16384
#define SV_OFF 32768
#define ST_OFF 51200
#define ATTN_SMEM_FLOATS (16384 + 16384 + 18432 + 1056)
#define ATTN_SMEM_BYTES (ATTN_SMEM_FLOATS * 4)

__global__ void k_attn(const __half* __restrict__ QKV, __half* __restrict__ O) {
    extern __shared__ float sm[];
    float* smq = sm + SQ_OFF;
    float* smk = sm + SK_OFF;
    float* smv = sm + SV_OFF;
    float* st  = sm + ST_OFF;
    int h = blockIdx.y;
    int t0 = blockIdx.x * AT;
    int tid = threadIdx.x;

    const __half* Qh = QKV;
    const __half* Kh = QKV + (size_t)512 * NN;
    const __half* Vh = QKV + (size_t)1024 * NN;

    for (int p0 = tid; p0 < 2048; p0 += 256) {
        int d = p0 >> 5, b = p0 & 31;
        size_t base = ((size_t)(h * 64 + d) * 32 + b) * 2048 + t0;
        uint4 qr = *(const uint4*)&Qh[base];
        uint4 kr = *(const uint4*)&Kh[base];
        uint4 vr = *(const uint4*)&Vh[base];
        __half2* qh = (__half2*)&qr;
        __half2* kh = (__half2*)&kr;
        __half2* vh = (__half2*)&vr;
        #pragma unroll
        for (int j = 0; j < 4; j++) {
            float2 qf = __half22float2(qh[j]);
            float2 kf = __half22float2(kh[j]);
            float2 vf = __half22float2(vh[j]);
            smq[((2 * j) * 64 + d) * 32 + b] = qf.x;
            smq[((2 * j + 1) * 64 + d) * 32 + b] = qf.y;
            smk[((2 * j) * 64 + d) * 32 + b] = kf.x;
            smk[((2 * j + 1) * 64 + d) * 32 + b] = kf.y;
            smv[((2 * j) * 64 + d) * 36 + b] = vf.x;
            smv[((2 * j + 1) * 64 + d) * 36 + b] = vf.y;
        }
    }
    __syncthreads();

    const float scale = 0.125f;
    int sb = tid >> 3, sp0 = (tid & 7) * 4;
    for (int ttk = 0; ttk < AT; ttk++) {
        float a0 = 0, a1 = 0, a2 = 0, a3 = 0;
        #pragma unroll
        for (int d = 0; d < 64; d++) {
            float qv = smq[(ttk * 64 + d) * 32 + sb];
            float4 kv = *(const float4*)&smk[(ttk * 64 + d) * 32 + sp0];
            a0 += qv * kv.x; a1 += qv * kv.y; a2 += qv * kv.z; a3 += qv * kv.w;
        }
        st[sb * 33 + sp0 + 0] = a0 * scale;
        st[sb * 33 + sp0 + 1] = a1 * scale;
        st[sb * 33 + sp0 + 2] = a2 * scale;
        st[sb * 33 + sp0 + 3] = a3 * scale;
        __syncthreads();
        if (tid < 32) {
            const float* row = st + tid * 33;
            float mx = -1e30f;
            #pragma unroll
            for (int j = 0; j < 32; j++) mx = fmaxf(mx, row[j]);
            float ev[32]; float sum = 0.0f;
            #pragma unroll
            for (int j = 0; j < 32; j++) { ev[j] = expf(row[j] - mx); sum += ev[j]; }
            float inv = 1.0f / sum;
            #pragma unroll
            for (int j = 0; j < 32; j++) smq[ttk * 1152 + tid * 36 + j] = ev[j] * inv;
        }
        __syncthreads();
    }

    for (int rep = 0; rep < 8; rep++) {
        int o = tid + rep * 256;
        int ob = o >> 6, od = o & 63;
        float outv[8];
        #pragma unroll
        for (int s = 0; s < 8; s++) {
            float acc = 0.0f;
            #pragma unroll
            for (int bp = 0; bp < 32; bp += 4) {
                float4 pv = *(const float4*)&smq[s * 1152 + ob * 36 + bp];
                float4 vv = *(const float4*)&smv[(s * 64 + od) * 36 + bp];
                acc += pv.x * vv.x + pv.y * vv.y + pv.z * vv.z + pv.w * vv.w;
            }
            outv[s] = acc;
        }
        size_t base = ((size_t)(h * 64 + od) * 32 + ob) * 2048 + t0;
        __half2 h0 = __halves2half2(__float2half_rn(outv[0]), __float2half_rn(outv[1]));
        __half2 h1 = __halves2half2(__float2half_rn(outv[2]), __float2half_rn(outv[3]));
        __half2 h2 = __halves2half2(__float2half_rn(outv[4]), __float2half_rn(outv[5]));
        __half2 h3 = __halves2half2(__float2half_rn(outv[6]), __float2half_rn(outv[7]));
        uint4 w = { *(uint32_t*)&h0, *(uint32_t*)&h1, *(uint32_t*)&h2, *(uint32_t*)&h3 };
        *(uint4*)&O[base] = w;
    }
}

// ---------------- launch --------------------------------------------------
extern "C" void kernel_launch(void* const* d_in, const int* in_sizes, int n_in,
                              void* d_out, int out_size) {
    const float* x     = (const float*)d_in[0];
    const float* dw1_w = (const float*)d_in[1];
    const float* dw1_b = (const float*)d_in[2];
    const float* pw1_w = (const float*)d_in[3];
    const float* pw1_b = (const float*)d_in[4];
    const float* dw2_w = (const float*)d_in[5];
    const float* dw2_b = (const float*)d_in[6];
    const float* pw2_w = (const float*)d_in[7];
    const float* pw2_b = (const float*)d_in[8];
    const float* wq = (const float*)d_in[9];
    const float* bq = (const float*)d_in[10];
    const float* wk = (const float*)d_in[11];
    const float* bk = (const float*)d_in[12];
    const float* wv = (const float*)d_in[13];
    const float* bv = (const float*)d_in[14];
    const float* wp = (const float*)d_in[15];
    const float* bp = (const float*)d_in[16];
    const float* ff_w = (const float*)d_in[17];
    const float* ff_b = (const float*)d_in[18];
    float* out = (float*)d_out;

    float *pX, *pBqkv;
    __half *pBt, *pST, *pQKV, *pWb, *pWb2, *pWp, *pWff, *pWqkv;
    cudaGetSymbolAddress((void**)&pX, gX);
    cudaGetSymbolAddress((void**)&pBt, gBt);
    cudaGetSymbolAddress((void**)&pST, gST);
    cudaGetSymbolAddress((void**)&pQKV, gQKV);
    cudaGetSymbolAddress((void**)&pWb, gWb);
    cudaGetSymbolAddress((void**)&pWb2, gWb2);
    cudaGetSymbolAddress((void**)&pWp, gWp);
    cudaGetSymbolAddress((void**)&pWff, gWff);
    cudaGetSymbolAddress((void**)&pWqkv, gWqkv);
    cudaGetSymbolAddress((void**)&pBqkv, gBqkv);

    cudaFuncSetAttribute(k_attn, cudaFuncAttributeMaxDynamicSharedMemorySize, ATTN_SMEM_BYTES);
    cudaFuncSetAttribute((k_mma<0, 1, 0, float>), cudaFuncAttributeMaxDynamicSharedMemorySize, MMA_SMEM);
    cudaFuncSetAttribute((k_mma<1, 1, 0, float>), cudaFuncAttributeMaxDynamicSharedMemorySize, MMA_SMEM);
    cudaFuncSetAttribute((k_mma<0, 0, 0, __half>), cudaFuncAttributeMaxDynamicSharedMemorySize, MMA_SMEM);
    cudaFuncSetAttribute((k_mma<1, 2, 0, float>), cudaFuncAttributeMaxDynamicSharedMemorySize, MMA_SMEM);
    cudaFuncSetAttribute((k_mma<1, 0, 1, float>), cudaFuncAttributeMaxDynamicSharedMemorySize, MMA_SMEM);

    dim3 mmaG(4, 512);       // m fast -> B tiles shared across m via L2
    dim3 mmaGqkv(12, 512);
    dim3 trG(NN / 64, 8);    // fp16 transpose grid
    dim3 cvtG(NN / 32, CC / 32), cvtB32(32, 8);

    // 0) all weight converts in one kernel; input transpose + pos-enc (+stats)
    k_cvtall<<<7168, 256>>>(pw1_w, pw2_w, wp, ff_w, wq, wk, wv, bq, bk, bv,
                            pWb, pWb2, pWp, pWff, pWqkv, pBqkv);
    k_transpose_in<<<dim3(TT / 32, CC / 32, BB), dim3(32, 8)>>>(x, pX);
    k_bfinal<<<1, 32>>>();

    // 1) conv block 1: X = pw1 @ dwconv1(LN_b(X)) + b   (+batch stats)
    k_dwconv<<<dim3(CC, BB), 256>>>(pX, dw1_w, dw1_b, pST);
    k_tr16<<<trG, 256>>>(pST, pBt);
    k_mma<0, 1, 0, float><<<mmaG, 256, MMA_SMEM>>>(pWb, pBt, pw1_b, pX, pX);
    k_bfinal<<<1, 32>>>();

    // 2) conv blocks 2..4 (shared weights)
    for (int it = 0; it < 3; it++) {
        k_dwconv<<<dim3(CC, BB), 256>>>(pX, dw2_w, dw2_b, pST);
        k_tr16<<<trG, 256>>>(pST, pBt);
        k_mma<1, 1, 0, float><<<mmaG, 256, MMA_SMEM>>>(pWb2, pBt, pw2_b, pX, pX);
        k_bfinal<<<1, 32>>>();
    }

    // 3) attention over batch axis (merged QKV GEMM, fp16)
    k_cvtBt<1><<<cvtG, cvtB32>>>(pX, pBt);
    k_mma<0, 0, 0, __half><<<mmaGqkv, 256, MMA_SMEM>>>(pWqkv, pBt, pBqkv, pQKV, (const float*)0);
    k_attn<<<dim3(TT / AT, HH), 256, ATTN_SMEM_BYTES>>>(pQKV, pST);
    k_tr16<<<trG, 256>>>(pST, pBt);
    k_mma<1, 2, 0, float><<<mmaG, 256, MMA_SMEM>>>(pWp, pBt, bp, pX, pX);  // +per-t stats
    k_tfinal<<<TT / 256, 256>>>();

    // 4) FF with per-t LN; final GEMM writes output transposed (B,T,F)
    k_cvtBt<2><<<cvtG, cvtB32>>>(pX, pBt);
    k_mma<1, 0, 1, float><<<mmaG, 256, MMA_SMEM>>>(pWff, pBt, ff_b, out, pX);

    (void)in_sizes; (void)n_in; (void)out_size;
}

// round 11
// speedup vs baseline: 1.0145x; 1.0145x over previous
#include <cuda_runtime.h>
#include <cuda_fp16.h>
#include <cstdint>
#include <math.h>

// ---------------- problem constants ----------------
#define BB 32
#define TT 2048
#define CC 512          // E == F == 512
#define NN 65536        // B*T
#define HH 8
#define EPS 1e-5

// ---------------- scratch (device globals; allocation-free rule) ----------
__device__ float gX[33554432];     // state, layout (C, B, T) fp32
__device__ __half gBt[33554432];   // GEMM B operand, K-major [512][65536] fp16
__device__ __half gQKV[100663296]; // merged QKV output fp16 [1536][65536]
__device__ __half gWb[262144];     // pw1 weights fp16
__device__ __half gWb2[262144];    // pw2 weights fp16
__device__ __half gWp[262144];     // wp weights fp16
__device__ __half gWff[262144];    // ff weights fp16
__device__ __half gWqkv[786432];   // merged q|k|v weights fp16 [1536][512]
__device__ float gBqkv[1536];      // merged q|k|v bias

__device__ float g_bacc[64];       // per-batch (sum, sumsq) fp32 accumulators
__device__ float g_bmean[32], g_brstd[32];
__device__ float g_tacc[4096];     // per-t (sum, sumsq)
__device__ float g_tmean[2048], g_trstd[2048];

// ================= helpers =================
__device__ __forceinline__ uint32_t smem_u32(const void* p) {
    uint32_t a;
    asm("{ .reg .u64 t; cvta.to.shared.u64 t, %1; cvt.u32.u64 %0, t; }" : "=r"(a) : "l"(p));
    return a;
}
__device__ __forceinline__ void cp_async16(uint32_t smaddr, const void* g) {
    asm volatile("cp.async.cg.shared.global [%0], [%1], 16;" :: "r"(smaddr), "l"(g));
}
#define CP_COMMIT() asm volatile("cp.async.commit_group;" ::: "memory")
#define CP_WAIT1()  asm volatile("cp.async.wait_group 1;" ::: "memory")

__device__ __forceinline__ void ldmatrix_x4(uint32_t& r0, uint32_t& r1, uint32_t& r2,
                                            uint32_t& r3, uint32_t addr) {
    asm volatile("ldmatrix.sync.aligned.m8n8.x4.shared.b16 {%0,%1,%2,%3}, [%4];"
        : "=r"(r0), "=r"(r1), "=r"(r2), "=r"(r3) : "r"(addr));
}
__device__ __forceinline__ void ldmatrix_x4_trans(uint32_t& r0, uint32_t& r1, uint32_t& r2,
                                                  uint32_t& r3, uint32_t addr) {
    asm volatile("ldmatrix.sync.aligned.m8n8.x4.trans.shared.b16 {%0,%1,%2,%3}, [%4];"
        : "=r"(r0), "=r"(r1), "=r"(r2), "=r"(r3) : "r"(addr));
}
// fp16-accumulate MMA: D(2 regs fp16x2) = A*B + D
__device__ __forceinline__ void mma16816h(uint32_t* d, const uint32_t* a, uint32_t b0, uint32_t b1) {
    asm volatile(
        "mma.sync.aligned.m16n8k16.row.col.f16.f16.f16.f16 "
        "{%0,%1}, {%2,%3,%4,%5}, {%6,%7}, {%0,%1};"
        : "+r"(d[0]), "+r"(d[1])
        : "r"(a[0]), "r"(a[1]), "r"(a[2]), "r"(a[3]), "r"(b0), "r"(b1));
}

// ---------------- all weight converts + qkv pack in ONE kernel -------------
__global__ void k_cvtall(const float* __restrict__ pw1, const float* __restrict__ pw2,
                         const float* __restrict__ wp, const float* __restrict__ ffw,
                         const float* __restrict__ wq, const float* __restrict__ wk,
                         const float* __restrict__ wv, const float* __restrict__ bq,
                         const float* __restrict__ bk, const float* __restrict__ bv,
                         __half* __restrict__ W1, __half* __restrict__ W2,
                         __half* __restrict__ Wp, __half* __restrict__ Wff,
                         __half* __restrict__ Wqkv, float* __restrict__ Bqkv) {
    int idx = blockIdx.x * 256 + threadIdx.x;
    if (idx < 262144) {
        W1[idx] = __float2half_rn(pw1[idx]);
    } else if (idx < 524288) {
        int o = idx - 262144; W2[o] = __float2half_rn(pw2[o]);
    } else if (idx < 786432) {
        int o = idx - 524288; Wp[o] = __float2half_rn(wp[o]);
    } else if (idx < 1048576) {
        int o = idx - 786432; Wff[o] = __float2half_rn(ffw[o]);
    } else {
        int o2 = idx - 1048576;           // 0..786431
        int sel = o2 >> 18;
        int off = o2 & 262143;
        const float* src = (sel == 0) ? wq : ((sel == 1) ? wk : wv);
        Wqkv[o2] = __float2half_rn(src[off]);
        if (off < 512) {
            const float* bs = (sel == 0) ? bq : ((sel == 1) ? bk : bv);
            Bqkv[sel * 512 + off] = bs[off];
        }
    }
}

// ---------------- input transpose + positional encoding + batch stats ------
__global__ void k_transpose_in(const float* __restrict__ in, float* __restrict__ X) {
    __shared__ float tile[32][33];
    __shared__ float rs[256], rq[256];
    int b = blockIdx.z;
    int t0 = blockIdx.x * 32, c0 = blockIdx.y * 32;
    int tx = threadIdx.x, ty = threadIdx.y;
    #pragma unroll
    for (int i = ty; i < 32; i += 8)
        tile[i][tx] = in[((size_t)b * TT + t0 + i) * CC + c0 + tx];
    __syncthreads();
    float s = 0.0f, q = 0.0f;
    #pragma unroll
    for (int i = ty; i < 32; i += 8) {
        int c = c0 + i;
        float div = expf((float)(c & ~1) * (-9.210340371976184f / 512.0f));
        float ang = (float)b * div;
        float pe = (c & 1) ? cosf(ang) : sinf(ang);
        float v = tile[tx][i] + pe;
        X[((size_t)c * BB + b) * TT + t0 + tx] = v;
        s += v; q += v * v;
    }
    int tid = ty * 32 + tx;
    rs[tid] = s; rq[tid] = q;
    __syncthreads();
    for (int o = 128; o > 0; o >>= 1) {
        if (tid < o) { rs[tid] += rs[tid + o]; rq[tid] += rq[tid + o]; }
        __syncthreads();
    }
    if (tid == 0) {
        atomicAdd(&g_bacc[2 * b], rs[0]);
        atomicAdd(&g_bacc[2 * b + 1], rq[0]);
    }
}

// ---------------- finalize per-batch stats (and re-zero accumulators) ------
__global__ void k_bfinal() {
    int b = threadIdx.x;
    if (b < 32) {
        double s = (double)g_bacc[2 * b], q = (double)g_bacc[2 * b + 1];
        double n = 1048576.0;
        double mu = s / n;
        double var = q / n - mu * mu;
        g_bmean[b] = (float)mu;
        g_brstd[b] = (float)(1.0 / sqrt(var + (double)EPS));
        g_bacc[2 * b] = 0.0f;
        g_bacc[2 * b + 1] = 0.0f;
    }
}

// ---------------- finalize per-t stats ----------------
__global__ void k_tfinal() {
    int t = blockIdx.x * 256 + threadIdx.x;
    double s = (double)g_tacc[2 * t], q = (double)g_tacc[2 * t + 1];
    double n = 16384.0;
    double mu = s / n;
    double var = q / n - mu * mu;
    g_tmean[t] = (float)mu;
    g_trstd[t] = (float)(1.0 / sqrt(var + (double)EPS));
    g_tacc[2 * t] = 0.0f;
    g_tacc[2 * t + 1] = 0.0f;
}

// ---------------- fused per-batch-LN + depthwise conv (k=7) -> fp16 --------
__global__ void k_dwconv(const float* __restrict__ X, const float* __restrict__ dww,
                         const float* __restrict__ dwb, __half* __restrict__ D) {
    int c = blockIdx.x, b = blockIdx.y;
    int tid = threadIdx.x;
    __shared__ float s[TT + 16];   // x[t] at s[t+4]
    float mu = g_bmean[b], r = g_brstd[b];
    const float4* row4 = (const float4*)(X + ((size_t)c * BB + b) * TT);
    #pragma unroll
    for (int i = 0; i < 2; i++) {
        int t4 = tid + i * 256;
        float4 v = row4[t4];
        v.x = (v.x - mu) * r; v.y = (v.y - mu) * r;
        v.z = (v.z - mu) * r; v.w = (v.w - mu) * r;
        *(float4*)&s[4 + t4 * 4] = v;
    }
    if (tid < 4) s[tid] = 0.0f;
    else if (tid < 8) s[2048 + tid] = 0.0f;
    __syncthreads();
    float w0 = dww[c * 7 + 0], w1 = dww[c * 7 + 1], w2 = dww[c * 7 + 2], w3 = dww[c * 7 + 3];
    float w4 = dww[c * 7 + 4], w5 = dww[c * 7 + 5], w6 = dww[c * 7 + 6];
    float bias = dwb[c];
    int t0 = tid * 8;
    float xv[16];
    *(float4*)&xv[0]  = *(const float4*)&s[t0];
    *(float4*)&xv[4]  = *(const float4*)&s[t0 + 4];
    *(float4*)&xv[8]  = *(const float4*)&s[t0 + 8];
    *(float4*)&xv[12] = *(const float4*)&s[t0 + 12];
    __half2 oh[4];
    #pragma unroll
    for (int j = 0; j < 8; j += 2) {
        float a0 = bias, a1 = bias;
        a0 += w0 * xv[j + 1]; a1 += w0 * xv[j + 2];
        a0 += w1 * xv[j + 2]; a1 += w1 * xv[j + 3];
        a0 += w2 * xv[j + 3]; a1 += w2 * xv[j + 4];
        a0 += w3 * xv[j + 4]; a1 += w3 * xv[j + 5];
        a0 += w4 * xv[j + 5]; a1 += w4 * xv[j + 6];
        a0 += w5 * xv[j + 6]; a1 += w5 * xv[j + 7];
        a0 += w6 * xv[j + 7]; a1 += w6 * xv[j + 8];
        oh[j >> 1] = __halves2half2(__float2half_rn(a0), __float2half_rn(a1));
    }
    uint4 wv = { *(uint32_t*)&oh[0], *(uint32_t*)&oh[1], *(uint32_t*)&oh[2], *(uint32_t*)&oh[3] };
    *(uint4*)(D + ((size_t)c * BB + b) * TT + t0) = wv;
}

// ---------------- elementwise LN + fp32->fp16 (layout preserved) -----------
template <int MODE>
__global__ void k_cvtBe(const float* __restrict__ X, __half* __restrict__ Bt) {
    size_t i = ((size_t)blockIdx.x * 256 + threadIdx.x) * 4;
    float4 v = *(const float4*)&X[i];
    if (MODE == 1) {
        int b = (int)((i >> 11) & 31);
        float mu = g_bmean[b], sc = g_brstd[b];
        v.x = (v.x - mu) * sc; v.y = (v.y - mu) * sc;
        v.z = (v.z - mu) * sc; v.w = (v.w - mu) * sc;
    } else {
        int t0 = (int)(i & (TT - 1));
        float4 m = *(const float4*)&g_tmean[t0];
        float4 r = *(const float4*)&g_trstd[t0];
        v.x = (v.x - m.x) * r.x; v.y = (v.y - m.y) * r.y;
        v.z = (v.z - m.z) * r.z; v.w = (v.w - m.w) * r.w;
    }
    __half2 h0 = __halves2half2(__float2half_rn(v.x), __float2half_rn(v.y));
    __half2 h1 = __halves2half2(__float2half_rn(v.z), __float2half_rn(v.w));
    uint2 w = { *(uint32_t*)&h0, *(uint32_t*)&h1 };
    *(uint2*)&Bt[i] = w;
}

// ---------------- tensor-core GEMM: C[M,65536] (+)= W @ X + bias ------------
// A fp16 [M][512] row-major; B fp16 [512][65536] K-major.
// CTA 128x128, 8 warps (warp 64x32), K chunks of 64, 3-stage cp.async.
// fp16-accumulate MMA within each K-64 chunk (2 mf-half passes), folded to
// fp32 master accumulators per chunk.
#define KSTAGE 64
#define NSTG 3
#define A_BYTES 16384
#define STG_BYTES 32768
#define MMA_SMEM (NSTG * STG_BYTES)
#define NKC 8

template <int BETA, int STATS, int TRANS, typename OutT>
__global__ void __launch_bounds__(256, 2)
k_mma(const __half* __restrict__ Wb, const __half* __restrict__ Bt,
      const float* __restrict__ bias, OutT* __restrict__ C, const float* __restrict__ Cin) {
    extern __shared__ char dsm[];
    uint32_t smb = smem_u32(dsm);
    int tid = threadIdx.x;
    int wid = tid >> 5, lane = tid & 31;
    int m0 = blockIdx.x * 128, n0 = blockIdx.y * 128;
    int warp_m = wid >> 2, warp_n = wid & 3;

    float acc[4][4][4];
    #pragma unroll
    for (int a = 0; a < 4; a++)
        #pragma unroll
        for (int b = 0; b < 4; b++)
            #pragma unroll
            for (int c = 0; c < 4; c++) acc[a][b][c] = 0.0f;

    int arow = tid >> 3, ach = tid & 7;
    int brow = tid >> 4, bch = tid & 15;

    auto prefetch = [&](int st, int kc) {
        uint32_t sA = smb + st * STG_BYTES;
        uint32_t sB = sA + A_BYTES;
        #pragma unroll
        for (int i = 0; i < 4; i++) {
            int row = arow + i * 32;
            const __half* g = Wb + (size_t)(m0 + row) * 512 + kc * KSTAGE + ach * 8;
            cp_async16(sA + row * 128 + ((ach ^ (row & 7)) << 4), g);
        }
        #pragma unroll
        for (int i = 0; i < 4; i++) {
            int row = brow + i * 16;
            const __half* g = Bt + (size_t)(kc * KSTAGE + row) * NN + n0 + bch * 8;
            cp_async16(sB + row * 256 + ((bch ^ (row & 7)) << 4), g);
        }
    };

    prefetch(0, 0); CP_COMMIT();
    prefetch(1, 1); CP_COMMIT();

    int lr = lane & 7, lq = lane >> 3;
    int rowoff = lr + (lq & 1) * 8;
    int csel = lq >> 1;
    int bk_off = (lq & 1) * 8 + lr;
    int bn_half = lq >> 1;

    for (int i = 0; i < NKC; i++) {
        CP_WAIT1();
        __syncthreads();
        if (i + 2 < NKC) prefetch((i + 2) % NSTG, i + 2);
        CP_COMMIT();

        uint32_t sA = smb + (i % NSTG) * STG_BYTES;
        uint32_t sB = sA + A_BYTES;

        // two mf-half passes; each accumulates K=64 in fp16, then folds to fp32
        #pragma unroll
        for (int half = 0; half < 2; half++) {
            uint32_t facc[2][4][2];
            #pragma unroll
            for (int m2 = 0; m2 < 2; m2++)
                #pragma unroll
                for (int t = 0; t < 4; t++) { facc[m2][t][0] = 0u; facc[m2][t][1] = 0u; }

            #pragma unroll
            for (int kk = 0; kk < 4; kk++) {
                uint32_t bf[2][4];
                #pragma unroll
                for (int nf = 0; nf < 2; nf++) {
                    int krow = kk * 16 + bk_off;
                    int nch = warp_n * 4 + nf * 2 + bn_half;
                    ldmatrix_x4_trans(bf[nf][0], bf[nf][1], bf[nf][2], bf[nf][3],
                                      sB + krow * 256 + ((nch ^ (krow & 7)) << 4));
                }
                int chnk = kk * 2 + csel;
                uint32_t af[2][4];
                #pragma unroll
                for (int m2 = 0; m2 < 2; m2++) {
                    int row = warp_m * 64 + (half * 2 + m2) * 16 + rowoff;
                    ldmatrix_x4(af[m2][0], af[m2][1], af[m2][2], af[m2][3],
                                sA + row * 128 + ((chnk ^ (row & 7)) << 4));
                }
                #pragma unroll
                for (int m2 = 0; m2 < 2; m2++)
                    #pragma unroll
                    for (int t = 0; t < 4; t++)
                        mma16816h(facc[m2][t], af[m2],
                                  bf[t >> 1][(t & 1) * 2], bf[t >> 1][(t & 1) * 2 + 1]);
            }
            // fold fp16 group sums into fp32 masters
            #pragma unroll
            for (int m2 = 0; m2 < 2; m2++)
                #pragma unroll
                for (int t = 0; t < 4; t++) {
                    float2 f0 = __half22float2(*(__half2*)&facc[m2][t][0]);
                    float2 f1 = __half22float2(*(__half2*)&facc[m2][t][1]);
                    acc[half * 2 + m2][t][0] += f0.x;
                    acc[half * 2 + m2][t][1] += f0.y;
                    acc[half * 2 + m2][t][2] += f1.x;
                    acc[half * 2 + m2][t][3] += f1.y;
                }
        }
        // no trailing sync: leading sync of next iter protects stage reuse
    }
    __syncthreads();   // all mainloop SMEM reads done before epilogue reuses dsm

    // ---- epilogue ----
    float* colsum = (float*)dsm;        // STATS==2: [128] + [128]
    float* colsq  = colsum + 128;
    float* stg    = (float*)dsm;        // TRANS: [128][132]
    if (STATS == 2) {
        if (tid < 128) { colsum[tid] = 0.0f; colsq[tid] = 0.0f; }
        __syncthreads();
    }
    float s_part = 0.0f, q_part = 0.0f;
    int g = lane >> 2, tg = lane & 3;
    #pragma unroll
    for (int mf = 0; mf < 4; mf++) {
        int mlA = warp_m * 64 + mf * 16 + g;
        int mlB = mlA + 8;
        int mA = m0 + mlA, mB2 = m0 + mlB;
        float bva = bias[mA], bvb = bias[mB2];
        #pragma unroll
        for (int t = 0; t < 4; t++) {
            int nl = warp_n * 32 + t * 8 + tg * 2;
            int n = n0 + nl;
            size_t o0 = (size_t)mA * NN + n;
            size_t o1 = (size_t)mB2 * NN + n;
            float v00 = acc[mf][t][0] + bva, v01 = acc[mf][t][1] + bva;
            float v10 = acc[mf][t][2] + bvb, v11 = acc[mf][t][3] + bvb;
            if (BETA) {
                float2 p0 = *(const float2*)&Cin[o0];
                float2 p1 = *(const float2*)&Cin[o1];
                v00 += p0.x; v01 += p0.y;
                v10 += p1.x; v11 += p1.y;
            }
            if (STATS == 1) {
                s_part += v00 + v01 + v10 + v11;
                q_part += v00 * v00 + v01 * v01 + v10 * v10 + v11 * v11;
            }
            if (STATS == 2) {
                atomicAdd(&colsum[nl], v00 + v10);
                atomicAdd(&colsum[nl + 1], v01 + v11);
                atomicAdd(&colsq[nl], v00 * v00 + v10 * v10);
                atomicAdd(&colsq[nl + 1], v01 * v01 + v11 * v11);
            }
            if (TRANS) {
                stg[nl * 132 + mlA] = v00;
                stg[(nl + 1) * 132 + mlA] = v01;
                stg[nl * 132 + mlB] = v10;
                stg[(nl + 1) * 132 + mlB] = v11;
            } else if (sizeof(OutT) == 4) {
                float2 w0 = { v00, v01 }, w1 = { v10, v11 };
                *(float2*)&((float*)C)[o0] = w0;
                *(float2*)&((float*)C)[o1] = w1;
            } else {
                __half2 h0 = __halves2half2(__float2half_rn(v00), __float2half_rn(v01));
                __half2 h1 = __halves2half2(__float2half_rn(v10), __float2half_rn(v11));
                *(uint32_t*)&((__half*)C)[o0] = *(uint32_t*)&h0;
                *(uint32_t*)&((__half*)C)[o1] = *(uint32_t*)&h1;
            }
        }
    }
    if (STATS == 1) {
        float* red = (float*)dsm;
        red[tid] = s_part; red[256 + tid] = q_part;
        __syncthreads();
        for (int o = 128; o > 0; o >>= 1) {
            if (tid < o) { red[tid] += red[tid + o]; red[256 + tid] += red[256 + tid + o]; }
            __syncthreads();
        }
        if (tid == 0) {
            int b = n0 >> 11;
            atomicAdd(&g_bacc[2 * b], red[0]);
            atomicAdd(&g_bacc[2 * b + 1], red[256]);
        }
    }
    if (STATS == 2) {
        __syncthreads();
        if (tid < 128) {
            int t = (n0 + tid) & (TT - 1);
            atomicAdd(&g_tacc[2 * t], colsum[tid]);
            atomicAdd(&g_tacc[2 * t + 1], colsq[tid]);
        }
    }
    if (TRANS) {
        __syncthreads();
        int ml = tid & 127;
        for (int nl = tid >> 7; nl < 128; nl += 2)
            ((float*)C)[(size_t)(n0 + nl) * CC + m0 + ml] = stg[nl * 132 + ml];
    }
}

// ---------------- attention over the batch axis (fp16 QKV in, fp16 out) ----
#define AT 8
#define SQ_OFF 0
#define SK_OFF 16384
#define SV_OFF 32768
#define ST_OFF 51200
#define ATTN_SMEM_FLOATS (16384 + 16384 + 18432 + 1056)
#define ATTN_SMEM_BYTES (ATTN_SMEM_FLOATS * 4)

__global__ void k_attn(const __half* __restrict__ QKV, __half* __restrict__ O) {
    extern __shared__ float sm[];
    float* smq = sm + SQ_OFF;
    float* smk = sm + SK_OFF;
    float* smv = sm + SV_OFF;
    float* st  = sm + ST_OFF;
    int h = blockIdx.y;
    int t0 = blockIdx.x * AT;
    int tid = threadIdx.x;

    const __half* Qh = QKV;
    const __half* Kh = QKV + (size_t)512 * NN;
    const __half* Vh = QKV + (size_t)1024 * NN;

    for (int p0 = tid; p0 < 2048; p0 += 256) {
        int d = p0 >> 5, b = p0 & 31;
        size_t base = ((size_t)(h * 64 + d) * 32 + b) * 2048 + t0;
        uint4 qr = *(const uint4*)&Qh[base];
        uint4 kr = *(const uint4*)&Kh[base];
        uint4 vr = *(const uint4*)&Vh[base];
        __half2* qh = (__half2*)&qr;
        __half2* kh = (__half2*)&kr;
        __half2* vh = (__half2*)&vr;
        #pragma unroll
        for (int j = 0; j < 4; j++) {
            float2 qf = __half22float2(qh[j]);
            float2 kf = __half22float2(kh[j]);
            float2 vf = __half22float2(vh[j]);
            smq[((2 * j) * 64 + d) * 32 + b] = qf.x;
            smq[((2 * j + 1) * 64 + d) * 32 + b] = qf.y;
            smk[((2 * j) * 64 + d) * 32 + b] = kf.x;
            smk[((2 * j + 1) * 64 + d) * 32 + b] = kf.y;
            smv[((2 * j) * 64 + d) * 36 + b] = vf.x;
            smv[((2 * j + 1) * 64 + d) * 36 + b] = vf.y;
        }
    }
    __syncthreads();

    const float scale = 0.125f;
    int sb = tid >> 3, sp0 = (tid & 7) * 4;
    for (int ttk = 0; ttk < AT; ttk++) {
        float a0 = 0, a1 = 0, a2 = 0, a3 = 0;
        #pragma unroll
        for (int d = 0; d < 64; d++) {
            float qv = smq[(ttk * 64 + d) * 32 + sb];
            float4 kv = *(const float4*)&smk[(ttk * 64 + d) * 32 + sp0];
            a0 += qv * kv.x; a1 += qv * kv.y; a2 += qv * kv.z; a3 += qv * kv.w;
        }
        st[sb * 33 + sp0 + 0] = a0 * scale;
        st[sb * 33 + sp0 + 1] = a1 * scale;
        st[sb * 33 + sp0 + 2] = a2 * scale;
        st[sb * 33 + sp0 + 3] = a3 * scale;
        __syncthreads();
        if (tid < 32) {
            const float* row = st + tid * 33;
            float mx = -1e30f;
            #pragma unroll
            for (int j = 0; j < 32; j++) mx = fmaxf(mx, row[j]);
            float ev[32]; float sum = 0.0f;
            #pragma unroll
            for (int j = 0; j < 32; j++) { ev[j] = expf(row[j] - mx); sum += ev[j]; }
            float inv = 1.0f / sum;
            #pragma unroll
            for (int j = 0; j < 32; j++) smq[ttk * 1152 + tid * 36 + j] = ev[j] * inv;
        }
        __syncthreads();
    }

    for (int rep = 0; rep < 8; rep++) {
        int o = tid + rep * 256;
        int ob = o >> 6, od = o & 63;
        float outv[8];
        #pragma unroll
        for (int s = 0; s < 8; s++) {
            float acc = 0.0f;
            #pragma unroll
            for (int bp = 0; bp < 32; bp += 4) {
                float4 pv = *(const float4*)&smq[s * 1152 + ob * 36 + bp];
                float4 vv = *(const float4*)&smv[(s * 64 + od) * 36 + bp];
                acc += pv.x * vv.x + pv.y * vv.y + pv.z * vv.z + pv.w * vv.w;
            }
            outv[s] = acc;
        }
        size_t base = ((size_t)(h * 64 + od) * 32 + ob) * 2048 + t0;
        __half2 h0 = __halves2half2(__float2half_rn(outv[0]), __float2half_rn(outv[1]));
        __half2 h1 = __halves2half2(__float2half_rn(outv[2]), __float2half_rn(outv[3]));
        __half2 h2 = __halves2half2(__float2half_rn(outv[4]), __float2half_rn(outv[5]));
        __half2 h3 = __halves2half2(__float2half_rn(outv[6]), __float2half_rn(outv[7]));
        uint4 w = { *(uint32_t*)&h0, *(uint32_t*)&h1, *(uint32_t*)&h2, *(uint32_t*)&h3 };
        *(uint4*)&O[base] = w;
    }
}

// ---------------- launch --------------------------------------------------
extern "C" void kernel_launch(void* const* d_in, const int* in_sizes, int n_in,
                              void* d_out, int out_size) {
    const float* x     = (const float*)d_in[0];
    const float* dw1_w = (const float*)d_in[1];
    const float* dw1_b = (const float*)d_in[2];
    const float* pw1_w = (const float*)d_in[3];
    const float* pw1_b = (const float*)d_in[4];
    const float* dw2_w = (const float*)d_in[5];
    const float* dw2_b = (const float*)d_in[6];
    const float* pw2_w = (const float*)d_in[7];
    const float* pw2_b = (const float*)d_in[8];
    const float* wq = (const float*)d_in[9];
    const float* bq = (const float*)d_in[10];
    const float* wk = (const float*)d_in[11];
    const float* bk = (const float*)d_in[12];
    const float* wv = (const float*)d_in[13];
    const float* bv = (const float*)d_in[14];
    const float* wp = (const float*)d_in[15];
    const float* bp = (const float*)d_in[16];
    const float* ff_w = (const float*)d_in[17];
    const float* ff_b = (const float*)d_in[18];
    float* out = (float*)d_out;

    float *pX, *pBqkv;
    __half *pBt, *pQKV, *pWb, *pWb2, *pWp, *pWff, *pWqkv;
    cudaGetSymbolAddress((void**)&pX, gX);
    cudaGetSymbolAddress((void**)&pBt, gBt);
    cudaGetSymbolAddress((void**)&pQKV, gQKV);
    cudaGetSymbolAddress((void**)&pWb, gWb);
    cudaGetSymbolAddress((void**)&pWb2, gWb2);
    cudaGetSymbolAddress((void**)&pWp, gWp);
    cudaGetSymbolAddress((void**)&pWff, gWff);
    cudaGetSymbolAddress((void**)&pWqkv, gWqkv);
    cudaGetSymbolAddress((void**)&pBqkv, gBqkv);

    cudaFuncSetAttribute(k_attn, cudaFuncAttributeMaxDynamicSharedMemorySize, ATTN_SMEM_BYTES);
    cudaFuncSetAttribute((k_mma<0, 1, 0, float>), cudaFuncAttributeMaxDynamicSharedMemorySize, MMA_SMEM);
    cudaFuncSetAttribute((k_mma<1, 1, 0, float>), cudaFuncAttributeMaxDynamicSharedMemorySize, MMA_SMEM);
    cudaFuncSetAttribute((k_mma<0, 0, 0, __half>), cudaFuncAttributeMaxDynamicSharedMemorySize, MMA_SMEM);
    cudaFuncSetAttribute((k_mma<1, 2, 0, float>), cudaFuncAttributeMaxDynamicSharedMemorySize, MMA_SMEM);
    cudaFuncSetAttribute((k_mma<1, 0, 1, float>), cudaFuncAttributeMaxDynamicSharedMemorySize, MMA_SMEM);

    dim3 mmaG(4, 512);       // m fast -> B tiles shared across m via L2
    dim3 mmaGqkv(12, 512);

    // 0) all weight converts in one kernel; input transpose + pos-enc (+stats)
    k_cvtall<<<7168, 256>>>(pw1_w, pw2_w, wp, ff_w, wq, wk, wv, bq, bk, bv,
                            pWb, pWb2, pWp, pWff, pWqkv, pBqkv);
    k_transpose_in<<<dim3(TT / 32, CC / 32, BB), dim3(32, 8)>>>(x, pX);
    k_bfinal<<<1, 32>>>();

    // 1) conv block 1: X = pw1 @ dwconv1(LN_b(X)) + b   (+batch stats)
    k_dwconv<<<dim3(CC, BB), 256>>>(pX, dw1_w, dw1_b, pBt);
    k_mma<0, 1, 0, float><<<mmaG, 256, MMA_SMEM>>>(pWb, pBt, pw1_b, pX, pX);
    k_bfinal<<<1, 32>>>();

    // 2) conv blocks 2..4 (shared weights)
    for (int it = 0; it < 3; it++) {
        k_dwconv<<<dim3(CC, BB), 256>>>(pX, dw2_w, dw2_b, pBt);
        k_mma<1, 1, 0, float><<<mmaG, 256, MMA_SMEM>>>(pWb2, pBt, pw2_b, pX, pX);
        k_bfinal<<<1, 32>>>();
    }

    // 3) attention over batch axis (merged QKV GEMM, fp16)
    k_cvtBe<1><<<32768, 256>>>(pX, pBt);
    k_mma<0, 0, 0, __half><<<mmaGqkv, 256, MMA_SMEM>>>(pWqkv, pBt, pBqkv, pQKV, (const float*)0);
    k_attn<<<dim3(TT / AT, HH), 256, ATTN_SMEM_BYTES>>>(pQKV, pBt);
    k_mma<1, 2, 0, float><<<mmaG, 256, MMA_SMEM>>>(pWp, pBt, bp, pX, pX);  // +per-t stats
    k_tfinal<<<TT / 256, 256>>>();

    // 4) FF with per-t LN; final GEMM writes output transposed (B,T,F)
    k_cvtBe<2><<<32768, 256>>>(pX, pBt);
    k_mma<1, 0, 1, float><<<mmaG, 256, MMA_SMEM>>>(pWff, pBt, ff_b, out, pX);

    (void)in_sizes; (void)n_in; (void)out_size;
}

// round 12
// speedup vs baseline: 1.1185x; 1.1025x over previous
#include <cuda_runtime.h>
#include <cuda_fp16.h>
#include <cstdint>
#include <math.h>

// ---------------- problem constants ----------------
#define BB 32
#define TT 2048
#define CC 512          // E == F == 512
#define NN 65536        // B*T
#define HH 8
#define EPS 1e-5

// ---------------- scratch (device globals; allocation-free rule) ----------
__device__ float gX[33554432];     // state, layout (C, B, T) fp32
__device__ __half gBt[33554432];   // GEMM B operand, K-major [512][65536] fp16
__device__ __half gQKV[100663296]; // merged QKV output fp16 [1536][65536]
__device__ __half gWb[262144];     // pw1 weights fp16
__device__ __half gWb2[262144];    // pw2 weights fp16
__device__ __half gWp[262144];     // wp weights fp16
__device__ __half gWff[262144];    // ff weights fp16
__device__ __half gWqkv[786432];   // merged q|k|v weights fp16 [1536][512]
__device__ float gBqkv[1536];      // merged q|k|v bias

__device__ float g_bacc[64];       // per-batch (sum, sumsq) fp32 accumulators
__device__ float g_bmean[32], g_brstd[32];
__device__ float g_tacc[4096];     // per-t (sum, sumsq)
__device__ float g_tmean[2048], g_trstd[2048];

// ================= helpers =================
__device__ __forceinline__ uint32_t smem_u32(const void* p) {
    uint32_t a;
    asm("{ .reg .u64 t; cvta.to.shared.u64 t, %1; cvt.u32.u64 %0, t; }" : "=r"(a) : "l"(p));
    return a;
}
__device__ __forceinline__ void cp_async16(uint32_t smaddr, const void* g) {
    asm volatile("cp.async.cg.shared.global [%0], [%1], 16;" :: "r"(smaddr), "l"(g));
}
#define CP_COMMIT() asm volatile("cp.async.commit_group;" ::: "memory")
#define CP_WAIT1()  asm volatile("cp.async.wait_group 1;" ::: "memory")

__device__ __forceinline__ void ldmatrix_x4(uint32_t& r0, uint32_t& r1, uint32_t& r2,
                                            uint32_t& r3, uint32_t addr) {
    asm volatile("ldmatrix.sync.aligned.m8n8.x4.shared.b16 {%0,%1,%2,%3}, [%4];"
        : "=r"(r0), "=r"(r1), "=r"(r2), "=r"(r3) : "r"(addr));
}
__device__ __forceinline__ void ldmatrix_x4_trans(uint32_t& r0, uint32_t& r1, uint32_t& r2,
                                                  uint32_t& r3, uint32_t addr) {
    asm volatile("ldmatrix.sync.aligned.m8n8.x4.trans.shared.b16 {%0,%1,%2,%3}, [%4];"
        : "=r"(r0), "=r"(r1), "=r"(r2), "=r"(r3) : "r"(addr));
}
__device__ __forceinline__ void mma16816(float* d, const uint32_t* a, uint32_t b0, uint32_t b1) {
    asm volatile(
        "mma.sync.aligned.m16n8k16.row.col.f32.f16.f16.f32 "
        "{%0,%1,%2,%3}, {%4,%5,%6,%7}, {%8,%9}, {%0,%1,%2,%3};"
        : "+f"(d[0]), "+f"(d[1]), "+f"(d[2]), "+f"(d[3])
        : "r"(a[0]), "r"(a[1]), "r"(a[2]), "r"(a[3]), "r"(b0), "r"(b1));
}

// ---------------- all weight converts + qkv pack in ONE kernel -------------
__global__ void k_cvtall(const float* __restrict__ pw1, const float* __restrict__ pw2,
                         const float* __restrict__ wp, const float* __restrict__ ffw,
                         const float* __restrict__ wq, const float* __restrict__ wk,
                         const float* __restrict__ wv, const float* __restrict__ bq,
                         const float* __restrict__ bk, const float* __restrict__ bv,
                         __half* __restrict__ W1, __half* __restrict__ W2,
                         __half* __restrict__ Wp, __half* __restrict__ Wff,
                         __half* __restrict__ Wqkv, float* __restrict__ Bqkv) {
    int idx = blockIdx.x * 256 + threadIdx.x;
    if (idx < 262144) {
        W1[idx] = __float2half_rn(pw1[idx]);
    } else if (idx < 524288) {
        int o = idx - 262144; W2[o] = __float2half_rn(pw2[o]);
    } else if (idx < 786432) {
        int o = idx - 524288; Wp[o] = __float2half_rn(wp[o]);
    } else if (idx < 1048576) {
        int o = idx - 786432; Wff[o] = __float2half_rn(ffw[o]);
    } else {
        int o2 = idx - 1048576;           // 0..786431
        int sel = o2 >> 18;
        int off = o2 & 262143;
        const float* src = (sel == 0) ? wq : ((sel == 1) ? wk : wv);
        Wqkv[o2] = __float2half_rn(src[off]);
        if (off < 512) {
            const float* bs = (sel == 0) ? bq : ((sel == 1) ? bk : bv);
            Bqkv[sel * 512 + off] = bs[off];
        }
    }
}

// ---------------- input transpose + positional encoding + batch stats ------
__global__ void k_transpose_in(const float* __restrict__ in, float* __restrict__ X) {
    __shared__ float tile[32][33];
    __shared__ float rs[256], rq[256];
    int b = blockIdx.z;
    int t0 = blockIdx.x * 32, c0 = blockIdx.y * 32;
    int tx = threadIdx.x, ty = threadIdx.y;
    #pragma unroll
    for (int i = ty; i < 32; i += 8)
        tile[i][tx] = in[((size_t)b * TT + t0 + i) * CC + c0 + tx];
    __syncthreads();
    float s = 0.0f, q = 0.0f;
    #pragma unroll
    for (int i = ty; i < 32; i += 8) {
        int c = c0 + i;
        float div = expf((float)(c & ~1) * (-9.210340371976184f / 512.0f));
        float ang = (float)b * div;
        float pe = (c & 1) ? cosf(ang) : sinf(ang);
        float v = tile[tx][i] + pe;
        X[((size_t)c * BB + b) * TT + t0 + tx] = v;
        s += v; q += v * v;
    }
    int tid = ty * 32 + tx;
    rs[tid] = s; rq[tid] = q;
    __syncthreads();
    for (int o = 128; o > 0; o >>= 1) {
        if (tid < o) { rs[tid] += rs[tid + o]; rq[tid] += rq[tid + o]; }
        __syncthreads();
    }
    if (tid == 0) {
        atomicAdd(&g_bacc[2 * b], rs[0]);
        atomicAdd(&g_bacc[2 * b + 1], rq[0]);
    }
}

// ---------------- finalize per-batch stats (and re-zero accumulators) ------
__global__ void k_bfinal() {
    int b = threadIdx.x;
    if (b < 32) {
        double s = (double)g_bacc[2 * b], q = (double)g_bacc[2 * b + 1];
        double n = 1048576.0;
        double mu = s / n;
        double var = q / n - mu * mu;
        g_bmean[b] = (float)mu;
        g_brstd[b] = (float)(1.0 / sqrt(var + (double)EPS));
        g_bacc[2 * b] = 0.0f;
        g_bacc[2 * b + 1] = 0.0f;
    }
}

// ---------------- finalize per-t stats ----------------
__global__ void k_tfinal() {
    int t = blockIdx.x * 256 + threadIdx.x;
    double s = (double)g_tacc[2 * t], q = (double)g_tacc[2 * t + 1];
    double n = 16384.0;
    double mu = s / n;
    double var = q / n - mu * mu;
    g_tmean[t] = (float)mu;
    g_trstd[t] = (float)(1.0 / sqrt(var + (double)EPS));
    g_tacc[2 * t] = 0.0f;
    g_tacc[2 * t + 1] = 0.0f;
}

// ---------------- fused per-batch-LN + depthwise conv (k=7) -> fp16 --------
__global__ void k_dwconv(const float* __restrict__ X, const float* __restrict__ dww,
                         const float* __restrict__ dwb, __half* __restrict__ D) {
    int c = blockIdx.x, b = blockIdx.y;
    int tid = threadIdx.x;
    __shared__ float s[TT + 16];   // x[t] at s[t+4]
    float mu = g_bmean[b], r = g_brstd[b];
    const float4* row4 = (const float4*)(X + ((size_t)c * BB + b) * TT);
    float4 v0 = row4[tid];
    float4 v1 = row4[tid + 256];
    v0.x = (v0.x - mu) * r; v0.y = (v0.y - mu) * r;
    v0.z = (v0.z - mu) * r; v0.w = (v0.w - mu) * r;
    v1.x = (v1.x - mu) * r; v1.y = (v1.y - mu) * r;
    v1.z = (v1.z - mu) * r; v1.w = (v1.w - mu) * r;
    *(float4*)&s[4 + tid * 4] = v0;
    *(float4*)&s[4 + (tid + 256) * 4] = v1;
    if (tid < 4) s[tid] = 0.0f;
    else if (tid < 8) s[2048 + tid] = 0.0f;
    __syncthreads();
    float w0 = dww[c * 7 + 0], w1 = dww[c * 7 + 1], w2 = dww[c * 7 + 2], w3 = dww[c * 7 + 3];
    float w4 = dww[c * 7 + 4], w5 = dww[c * 7 + 5], w6 = dww[c * 7 + 6];
    float bias = dwb[c];
    int t0 = tid * 8;
    float xv[16];
    *(float4*)&xv[0]  = *(const float4*)&s[t0];
    *(float4*)&xv[4]  = *(const float4*)&s[t0 + 4];
    *(float4*)&xv[8]  = *(const float4*)&s[t0 + 8];
    *(float4*)&xv[12] = *(const float4*)&s[t0 + 12];
    __half2 oh[4];
    #pragma unroll
    for (int j = 0; j < 8; j += 2) {
        float a0 = bias, a1 = bias;
        a0 += w0 * xv[j + 1]; a1 += w0 * xv[j + 2];
        a0 += w1 * xv[j + 2]; a1 += w1 * xv[j + 3];
        a0 += w2 * xv[j + 3]; a1 += w2 * xv[j + 4];
        a0 += w3 * xv[j + 4]; a1 += w3 * xv[j + 5];
        a0 += w4 * xv[j + 5]; a1 += w4 * xv[j + 6];
        a0 += w5 * xv[j + 6]; a1 += w5 * xv[j + 7];
        a0 += w6 * xv[j + 7]; a1 += w6 * xv[j + 8];
        oh[j >> 1] = __halves2half2(__float2half_rn(a0), __float2half_rn(a1));
    }
    uint4 wv = { *(uint32_t*)&oh[0], *(uint32_t*)&oh[1], *(uint32_t*)&oh[2], *(uint32_t*)&oh[3] };
    *(uint4*)(D + ((size_t)c * BB + b) * TT + t0) = wv;
}

// ---------------- elementwise LN + fp32->fp16 (8 elems/thread) -------------
// MODE 1: per-batch LN; MODE 2: per-t LN
template <int MODE>
__global__ void k_cvtBe(const float* __restrict__ X, __half* __restrict__ Bt) {
    size_t i = ((size_t)blockIdx.x * 256 + threadIdx.x) * 8;
    float4 v0 = *(const float4*)&X[i];
    float4 v1 = *(const float4*)&X[i + 4];
    if (MODE == 1) {
        int b = (int)((i >> 11) & 31);
        float mu = g_bmean[b], sc = g_brstd[b];
        v0.x = (v0.x - mu) * sc; v0.y = (v0.y - mu) * sc;
        v0.z = (v0.z - mu) * sc; v0.w = (v0.w - mu) * sc;
        v1.x = (v1.x - mu) * sc; v1.y = (v1.y - mu) * sc;
        v1.z = (v1.z - mu) * sc; v1.w = (v1.w - mu) * sc;
    } else {
        int t0 = (int)(i & (TT - 1));
        float4 m0 = *(const float4*)&g_tmean[t0];
        float4 r0 = *(const float4*)&g_trstd[t0];
        float4 m1 = *(const float4*)&g_tmean[t0 + 4];
        float4 r1 = *(const float4*)&g_trstd[t0 + 4];
        v0.x = (v0.x - m0.x) * r0.x; v0.y = (v0.y - m0.y) * r0.y;
        v0.z = (v0.z - m0.z) * r0.z; v0.w = (v0.w - m0.w) * r0.w;
        v1.x = (v1.x - m1.x) * r1.x; v1.y = (v1.y - m1.y) * r1.y;
        v1.z = (v1.z - m1.z) * r1.z; v1.w = (v1.w - m1.w) * r1.w;
    }
    __half2 h0 = __halves2half2(__float2half_rn(v0.x), __float2half_rn(v0.y));
    __half2 h1 = __halves2half2(__float2half_rn(v0.z), __float2half_rn(v0.w));
    __half2 h2 = __halves2half2(__float2half_rn(v1.x), __float2half_rn(v1.y));
    __half2 h3 = __halves2half2(__float2half_rn(v1.z), __float2half_rn(v1.w));
    uint4 w = { *(uint32_t*)&h0, *(uint32_t*)&h1, *(uint32_t*)&h2, *(uint32_t*)&h3 };
    *(uint4*)&Bt[i] = w;
}

// ---------------- tensor-core GEMM: C[M,65536] (+)= W @ X + bias ------------
// A fp16 [M][512] row-major; B fp16 [512][65536] K-major.
// CTA 128x128, 8 warps (warp 64x32), K chunks of 64, 3-stage cp.async.
// Mainloop: 1 sync per chunk; B fragments double-buffered across kk. (round-9 best)
#define KSTAGE 64
#define NSTG 3
#define A_BYTES 16384
#define STG_BYTES 32768
#define MMA_SMEM (NSTG * STG_BYTES)
#define NKC 8

template <int BETA, int STATS, int TRANS, typename OutT>
__global__ void __launch_bounds__(256, 2)
k_mma(const __half* __restrict__ Wb, const __half* __restrict__ Bt,
      const float* __restrict__ bias, OutT* __restrict__ C, const float* __restrict__ Cin) {
    extern __shared__ char dsm[];
    uint32_t smb = smem_u32(dsm);
    int tid = threadIdx.x;
    int wid = tid >> 5, lane = tid & 31;
    int m0 = blockIdx.x * 128, n0 = blockIdx.y * 128;
    int warp_m = wid >> 2, warp_n = wid & 3;

    float acc[4][4][4];
    #pragma unroll
    for (int a = 0; a < 4; a++)
        #pragma unroll
        for (int b = 0; b < 4; b++)
            #pragma unroll
            for (int c = 0; c < 4; c++) acc[a][b][c] = 0.0f;

    int arow = tid >> 3, ach = tid & 7;
    int brow = tid >> 4, bch = tid & 15;

    auto prefetch = [&](int st, int kc) {
        uint32_t sA = smb + st * STG_BYTES;
        uint32_t sB = sA + A_BYTES;
        #pragma unroll
        for (int i = 0; i < 4; i++) {
            int row = arow + i * 32;
            const __half* g = Wb + (size_t)(m0 + row) * 512 + kc * KSTAGE + ach * 8;
            cp_async16(sA + row * 128 + ((ach ^ (row & 7)) << 4), g);
        }
        #pragma unroll
        for (int i = 0; i < 4; i++) {
            int row = brow + i * 16;
            const __half* g = Bt + (size_t)(kc * KSTAGE + row) * NN + n0 + bch * 8;
            cp_async16(sB + row * 256 + ((bch ^ (row & 7)) << 4), g);
        }
    };

    prefetch(0, 0); CP_COMMIT();
    prefetch(1, 1); CP_COMMIT();

    int lr = lane & 7, lq = lane >> 3;
    int rowoff = lr + (lq & 1) * 8;
    int csel = lq >> 1;
    int bk_off = (lq & 1) * 8 + lr;
    int bn_half = lq >> 1;

    for (int i = 0; i < NKC; i++) {
        CP_WAIT1();
        __syncthreads();
        if (i + 2 < NKC) prefetch((i + 2) % NSTG, i + 2);
        CP_COMMIT();

        uint32_t sA = smb + (i % NSTG) * STG_BYTES;
        uint32_t sB = sA + A_BYTES;

        uint32_t bf[2][2][4];
        // preload B fragments for kk = 0
        #pragma unroll
        for (int nf = 0; nf < 2; nf++) {
            int krow = bk_off;
            int nch = warp_n * 4 + nf * 2 + bn_half;
            ldmatrix_x4_trans(bf[0][nf][0], bf[0][nf][1], bf[0][nf][2], bf[0][nf][3],
                              sB + krow * 256 + ((nch ^ (krow & 7)) << 4));
        }
        #pragma unroll
        for (int kk = 0; kk < 4; kk++) {
            int cur = kk & 1;
            if (kk < 3) {   // prefetch B fragments of kk+1 into the other buffer
                #pragma unroll
                for (int nf = 0; nf < 2; nf++) {
                    int krow = (kk + 1) * 16 + bk_off;
                    int nch = warp_n * 4 + nf * 2 + bn_half;
                    ldmatrix_x4_trans(bf[cur ^ 1][nf][0], bf[cur ^ 1][nf][1],
                                      bf[cur ^ 1][nf][2], bf[cur ^ 1][nf][3],
                                      sB + krow * 256 + ((nch ^ (krow & 7)) << 4));
                }
            }
            int chnk = kk * 2 + csel;
            uint32_t af[4][4];
            #pragma unroll
            for (int mf = 0; mf < 4; mf++) {
                int row = warp_m * 64 + mf * 16 + rowoff;
                ldmatrix_x4(af[mf][0], af[mf][1], af[mf][2], af[mf][3],
                            sA + row * 128 + ((chnk ^ (row & 7)) << 4));
            }
            #pragma unroll
            for (int mf = 0; mf < 4; mf++)
                #pragma unroll
                for (int t = 0; t < 4; t++)
                    mma16816(acc[mf][t], af[mf],
                             bf[cur][t >> 1][(t & 1) * 2], bf[cur][t >> 1][(t & 1) * 2 + 1]);
        }
        // no trailing sync: leading sync of next iter protects stage reuse
    }
    __syncthreads();   // all mainloop SMEM reads done before epilogue reuses dsm

    // ---- epilogue ----
    float* colsum = (float*)dsm;        // STATS==2: [128] + [128]
    float* colsq  = colsum + 128;
    float* stg    = (float*)dsm;        // TRANS: [128][132]
    if (STATS == 2) {
        if (tid < 128) { colsum[tid] = 0.0f; colsq[tid] = 0.0f; }
        __syncthreads();
    }
    float s_part = 0.0f, q_part = 0.0f;
    int g = lane >> 2, tg = lane & 3;
    #pragma unroll
    for (int mf = 0; mf < 4; mf++) {
        int mlA = warp_m * 64 + mf * 16 + g;
        int mlB = mlA + 8;
        int mA = m0 + mlA, mB2 = m0 + mlB;
        float bva = bias[mA], bvb = bias[mB2];
        #pragma unroll
        for (int t = 0; t < 4; t++) {
            int nl = warp_n * 32 + t * 8 + tg * 2;
            int n = n0 + nl;
            size_t o0 = (size_t)mA * NN + n;
            size_t o1 = (size_t)mB2 * NN + n;
            float v00 = acc[mf][t][0] + bva, v01 = acc[mf][t][1] + bva;
            float v10 = acc[mf][t][2] + bvb, v11 = acc[mf][t][3] + bvb;
            if (BETA) {
                float2 p0 = *(const float2*)&Cin[o0];
                float2 p1 = *(const float2*)&Cin[o1];
                v00 += p0.x; v01 += p0.y;
                v10 += p1.x; v11 += p1.y;
            }
            if (STATS == 1) {
                s_part += v00 + v01 + v10 + v11;
                q_part += v00 * v00 + v01 * v01 + v10 * v10 + v11 * v11;
            }
            if (STATS == 2) {
                atomicAdd(&colsum[nl], v00 + v10);
                atomicAdd(&colsum[nl + 1], v01 + v11);
                atomicAdd(&colsq[nl], v00 * v00 + v10 * v10);
                atomicAdd(&colsq[nl + 1], v01 * v01 + v11 * v11);
            }
            if (TRANS) {
                stg[nl * 132 + mlA] = v00;
                stg[(nl + 1) * 132 + mlA] = v01;
                stg[nl * 132 + mlB] = v10;
                stg[(nl + 1) * 132 + mlB] = v11;
            } else if (sizeof(OutT) == 4) {
                float2 w0 = { v00, v01 }, w1 = { v10, v11 };
                *(float2*)&((float*)C)[o0] = w0;
                *(float2*)&((float*)C)[o1] = w1;
            } else {
                __half2 h0 = __halves2half2(__float2half_rn(v00), __float2half_rn(v01));
                __half2 h1 = __halves2half2(__float2half_rn(v10), __float2half_rn(v11));
                *(uint32_t*)&((__half*)C)[o0] = *(uint32_t*)&h0;
                *(uint32_t*)&((__half*)C)[o1] = *(uint32_t*)&h1;
            }
        }
    }
    if (STATS == 1) {
        float* red = (float*)dsm;
        red[tid] = s_part; red[256 + tid] = q_part;
        __syncthreads();
        for (int o = 128; o > 0; o >>= 1) {
            if (tid < o) { red[tid] += red[tid + o]; red[256 + tid] += red[256 + tid + o]; }
            __syncthreads();
        }
        if (tid == 0) {
            int b = n0 >> 11;
            atomicAdd(&g_bacc[2 * b], red[0]);
            atomicAdd(&g_bacc[2 * b + 1], red[256]);
        }
    }
    if (STATS == 2) {
        __syncthreads();
        if (tid < 128) {
            int t = (n0 + tid) & (TT - 1);
            atomicAdd(&g_tacc[2 * t], colsum[tid]);
            atomicAdd(&g_tacc[2 * t + 1], colsq[tid]);
        }
    }
    if (TRANS) {
        __syncthreads();
        int ml = tid & 127;
        for (int nl = tid >> 7; nl < 128; nl += 2)
            ((float*)C)[(size_t)(n0 + nl) * CC + m0 + ml] = stg[nl * 132 + ml];
    }
}

// ---------------- attention over the batch axis (fp16 QKV in, fp16 out) ----
#define AT 8
#define SQ_OFF 0
#define SK_OFF 16384
#define SV_OFF 32768
#define ST_OFF 51200
#define ATTN_SMEM_FLOATS (16384 + 16384 + 18432 + 1056)
#define ATTN_SMEM_BYTES (ATTN_SMEM_FLOATS * 4)

__global__ void k_attn(const __half* __restrict__ QKV, __half* __restrict__ O) {
    extern __shared__ float sm[];
    float* smq = sm + SQ_OFF;
    float* smk = sm + SK_OFF;
    float* smv = sm + SV_OFF;
    float* st  = sm + ST_OFF;
    int h = blockIdx.y;
    int t0 = blockIdx.x * AT;
    int tid = threadIdx.x;

    const __half* Qh = QKV;
    const __half* Kh = QKV + (size_t)512 * NN;
    const __half* Vh = QKV + (size_t)1024 * NN;

    for (int p0 = tid; p0 < 2048; p0 += 256) {
        int d = p0 >> 5, b = p0 & 31;
        size_t base = ((size_t)(h * 64 + d) * 32 + b) * 2048 + t0;
        uint4 qr = *(const uint4*)&Qh[base];
        uint4 kr = *(const uint4*)&Kh[base];
        uint4 vr = *(const uint4*)&Vh[base];
        __half2* qh = (__half2*)&qr;
        __half2* kh = (__half2*)&kr;
        __half2* vh = (__half2*)&vr;
        #pragma unroll
        for (int j = 0; j < 4; j++) {
            float2 qf = __half22float2(qh[j]);
            float2 kf = __half22float2(kh[j]);
            float2 vf = __half22float2(vh[j]);
            smq[((2 * j) * 64 + d) * 32 + b] = qf.x;
            smq[((2 * j + 1) * 64 + d) * 32 + b] = qf.y;
            smk[((2 * j) * 64 + d) * 32 + b] = kf.x;
            smk[((2 * j + 1) * 64 + d) * 32 + b] = kf.y;
            smv[((2 * j) * 64 + d) * 36 + b] = vf.x;
            smv[((2 * j + 1) * 64 + d) * 36 + b] = vf.y;
        }
    }
    __syncthreads();

    const float scale = 0.125f;
    int sb = tid >> 3, sp0 = (tid & 7) * 4;
    for (int ttk = 0; ttk < AT; ttk++) {
        float a0 = 0, a1 = 0, a2 = 0, a3 = 0;
        #pragma unroll
        for (int d = 0; d < 64; d++) {
            float qv = smq[(ttk * 64 + d) * 32 + sb];
            float4 kv = *(const float4*)&smk[(ttk * 64 + d) * 32 + sp0];
            a0 += qv * kv.x; a1 += qv * kv.y; a2 += qv * kv.z; a3 += qv * kv.w;
        }
        st[sb * 33 + sp0 + 0] = a0 * scale;
        st[sb * 33 + sp0 + 1] = a1 * scale;
        st[sb * 33 + sp0 + 2] = a2 * scale;
        st[sb * 33 + sp0 + 3] = a3 * scale;
        __syncthreads();
        if (tid < 32) {
            const float* row = st + tid * 33;
            float mx = -1e30f;
            #pragma unroll
            for (int j = 0; j < 32; j++) mx = fmaxf(mx, row[j]);
            float ev[32]; float sum = 0.0f;
            #pragma unroll
            for (int j = 0; j < 32; j++) { ev[j] = expf(row[j] - mx); sum += ev[j]; }
            float inv = 1.0f / sum;
            #pragma unroll
            for (int j = 0; j < 32; j++) smq[ttk * 1152 + tid * 36 + j] = ev[j] * inv;
        }
        __syncthreads();
    }

    for (int rep = 0; rep < 8; rep++) {
        int o = tid + rep * 256;
        int ob = o >> 6, od = o & 63;
        float outv[8];
        #pragma unroll
        for (int s = 0; s < 8; s++) {
            float acc = 0.0f;
            #pragma unroll
            for (int bp = 0; bp < 32; bp += 4) {
                float4 pv = *(const float4*)&smq[s * 1152 + ob * 36 + bp];
                float4 vv = *(const float4*)&smv[(s * 64 + od) * 36 + bp];
                acc += pv.x * vv.x + pv.y * vv.y + pv.z * vv.z + pv.w * vv.w;
            }
            outv[s] = acc;
        }
        size_t base = ((size_t)(h * 64 + od) * 32 + ob) * 2048 + t0;
        __half2 h0 = __halves2half2(__float2half_rn(outv[0]), __float2half_rn(outv[1]));
        __half2 h1 = __halves2half2(__float2half_rn(outv[2]), __float2half_rn(outv[3]));
        __half2 h2 = __halves2half2(__float2half_rn(outv[4]), __float2half_rn(outv[5]));
        __half2 h3 = __halves2half2(__float2half_rn(outv[6]), __float2half_rn(outv[7]));
        uint4 w = { *(uint32_t*)&h0, *(uint32_t*)&h1, *(uint32_t*)&h2, *(uint32_t*)&h3 };
        *(uint4*)&O[base] = w;
    }
}

// ---------------- launch --------------------------------------------------
extern "C" void kernel_launch(void* const* d_in, const int* in_sizes, int n_in,
                              void* d_out, int out_size) {
    const float* x     = (const float*)d_in[0];
    const float* dw1_w = (const float*)d_in[1];
    const float* dw1_b = (const float*)d_in[2];
    const float* pw1_w = (const float*)d_in[3];
    const float* pw1_b = (const float*)d_in[4];
    const float* dw2_w = (const float*)d_in[5];
    const float* dw2_b = (const float*)d_in[6];
    const float* pw2_w = (const float*)d_in[7];
    const float* pw2_b = (const float*)d_in[8];
    const float* wq = (const float*)d_in[9];
    const float* bq = (const float*)d_in[10];
    const float* wk = (const float*)d_in[11];
    const float* bk = (const float*)d_in[12];
    const float* wv = (const float*)d_in[13];
    const float* bv = (const float*)d_in[14];
    const float* wp = (const float*)d_in[15];
    const float* bp = (const float*)d_in[16];
    const float* ff_w = (const float*)d_in[17];
    const float* ff_b = (const float*)d_in[18];
    float* out = (float*)d_out;

    float *pX, *pBqkv;
    __half *pBt, *pQKV, *pWb, *pWb2, *pWp, *pWff, *pWqkv;
    cudaGetSymbolAddress((void**)&pX, gX);
    cudaGetSymbolAddress((void**)&pBt, gBt);
    cudaGetSymbolAddress((void**)&pQKV, gQKV);
    cudaGetSymbolAddress((void**)&pWb, gWb);
    cudaGetSymbolAddress((void**)&pWb2, gWb2);
    cudaGetSymbolAddress((void**)&pWp, gWp);
    cudaGetSymbolAddress((void**)&pWff, gWff);
    cudaGetSymbolAddress((void**)&pWqkv, gWqkv);
    cudaGetSymbolAddress((void**)&pBqkv, gBqkv);

    cudaFuncSetAttribute(k_attn, cudaFuncAttributeMaxDynamicSharedMemorySize, ATTN_SMEM_BYTES);
    cudaFuncSetAttribute((k_mma<0, 1, 0, float>), cudaFuncAttributeMaxDynamicSharedMemorySize, MMA_SMEM);
    cudaFuncSetAttribute((k_mma<1, 1, 0, float>), cudaFuncAttributeMaxDynamicSharedMemorySize, MMA_SMEM);
    cudaFuncSetAttribute((k_mma<0, 0, 0, __half>), cudaFuncAttributeMaxDynamicSharedMemorySize, MMA_SMEM);
    cudaFuncSetAttribute((k_mma<1, 2, 0, float>), cudaFuncAttributeMaxDynamicSharedMemorySize, MMA_SMEM);
    cudaFuncSetAttribute((k_mma<1, 0, 1, float>), cudaFuncAttributeMaxDynamicSharedMemorySize, MMA_SMEM);

    dim3 mmaG(4, 512);       // m fast -> B tiles shared across m via L2
    dim3 mmaGqkv(12, 512);

    // 0) all weight converts in one kernel; input transpose + pos-enc (+stats)
    k_cvtall<<<7168, 256>>>(pw1_w, pw2_w, wp, ff_w, wq, wk, wv, bq, bk, bv,
                            pWb, pWb2, pWp, pWff, pWqkv, pBqkv);
    k_transpose_in<<<dim3(TT / 32, CC / 32, BB), dim3(32, 8)>>>(x, pX);
    k_bfinal<<<1, 32>>>();

    // 1) conv block 1: X = pw1 @ dwconv1(LN_b(X)) + b   (+batch stats)
    k_dwconv<<<dim3(CC, BB), 256>>>(pX, dw1_w, dw1_b, pBt);
    k_mma<0, 1, 0, float><<<mmaG, 256, MMA_SMEM>>>(pWb, pBt, pw1_b, pX, pX);
    k_bfinal<<<1, 32>>>();

    // 2) conv blocks 2..4 (shared weights)
    for (int it = 0; it < 3; it++) {
        k_dwconv<<<dim3(CC, BB), 256>>>(pX, dw2_w, dw2_b, pBt);
        k_mma<1, 1, 0, float><<<mmaG, 256, MMA_SMEM>>>(pWb2, pBt, pw2_b, pX, pX);
        k_bfinal<<<1, 32>>>();
    }

    // 3) attention over batch axis (merged QKV GEMM, fp16)
    k_cvtBe<1><<<16384, 256>>>(pX, pBt);
    k_mma<0, 0, 0, __half><<<mmaGqkv, 256, MMA_SMEM>>>(pWqkv, pBt, pBqkv, pQKV, (const float*)0);
    k_attn<<<dim3(TT / AT, HH), 256, ATTN_SMEM_BYTES>>>(pQKV, pBt);
    k_mma<1, 2, 0, float><<<mmaG, 256, MMA_SMEM>>>(pWp, pBt, bp, pX, pX);  // +per-t stats
    k_tfinal<<<TT / 256, 256>>>();

    // 4) FF with per-t LN; final GEMM writes output transposed (B,T,F)
    k_cvtBe<2><<<16384, 256>>>(pX, pBt);
    k_mma<1, 0, 1, float><<<mmaG, 256, MMA_SMEM>>>(pWff, pBt, ff_b, out, pX);

    (void)in_sizes; (void)n_in; (void)out_size;
}

// round 13
// speedup vs baseline: 1.1314x; 1.0115x over previous
#include <cuda_runtime.h>
#include <cuda_fp16.h>
#include <cstdint>
#include <math.h>

// ---------------- problem constants ----------------
#define BB 32
#define TT 2048
#define CC 512          // E == F == 512
#define NN 65536        // B*T
#define HH 8
#define EPS 1e-5
#define INV_BN 9.5367431640625e-7f    // 1/1048576

// ---------------- scratch (device globals; allocation-free rule) ----------
__device__ float gX[33554432];     // state, layout (C, B, T) fp32
__device__ __half gBt[33554432];   // GEMM B operand, K-major [512][65536] fp16
__device__ __half gQKV[100663296]; // merged QKV output fp16 [1536][65536]
__device__ __half gWb[262144];     // pw1 weights fp16
__device__ __half gWb2[262144];    // pw2 weights fp16
__device__ __half gWp[262144];     // wp weights fp16
__device__ __half gWff[262144];    // ff weights fp16
__device__ __half gWqkv[786432];   // merged q|k|v weights fp16 [1536][512]
__device__ float gBqkv[1536];      // merged q|k|v bias

__device__ float g_bst[5 * 64];    // staged per-batch (sum, sumsq): 5 stages x 32 b
__device__ float g_tacc[4096];     // per-t (sum, sumsq)
__device__ float g_tmean[2048], g_trstd[2048];

// ================= helpers =================
__device__ __forceinline__ uint32_t smem_u32(const void* p) {
    uint32_t a;
    asm("{ .reg .u64 t; cvta.to.shared.u64 t, %1; cvt.u32.u64 %0, t; }" : "=r"(a) : "l"(p));
    return a;
}
__device__ __forceinline__ void cp_async16(uint32_t smaddr, const void* g) {
    asm volatile("cp.async.cg.shared.global [%0], [%1], 16;" :: "r"(smaddr), "l"(g));
}
#define CP_COMMIT() asm volatile("cp.async.commit_group;" ::: "memory")
#define CP_WAIT1()  asm volatile("cp.async.wait_group 1;" ::: "memory")

__device__ __forceinline__ void ldmatrix_x4(uint32_t& r0, uint32_t& r1, uint32_t& r2,
                                            uint32_t& r3, uint32_t addr) {
    asm volatile("ldmatrix.sync.aligned.m8n8.x4.shared.b16 {%0,%1,%2,%3}, [%4];"
        : "=r"(r0), "=r"(r1), "=r"(r2), "=r"(r3) : "r"(addr));
}
__device__ __forceinline__ void ldmatrix_x4_trans(uint32_t& r0, uint32_t& r1, uint32_t& r2,
                                                  uint32_t& r3, uint32_t addr) {
    asm volatile("ldmatrix.sync.aligned.m8n8.x4.trans.shared.b16 {%0,%1,%2,%3}, [%4];"
        : "=r"(r0), "=r"(r1), "=r"(r2), "=r"(r3) : "r"(addr));
}
__device__ __forceinline__ void mma16816(float* d, const uint32_t* a, uint32_t b0, uint32_t b1) {
    asm volatile(
        "mma.sync.aligned.m16n8k16.row.col.f32.f16.f16.f32 "
        "{%0,%1,%2,%3}, {%4,%5,%6,%7}, {%8,%9}, {%0,%1,%2,%3};"
        : "+f"(d[0]), "+f"(d[1]), "+f"(d[2]), "+f"(d[3])
        : "r"(a[0]), "r"(a[1]), "r"(a[2]), "r"(a[3]), "r"(b0), "r"(b1));
}

// ---------------- all weight converts + qkv pack + stat zeroing ------------
__global__ void k_cvtall(const float* __restrict__ pw1, const float* __restrict__ pw2,
                         const float* __restrict__ wp, const float* __restrict__ ffw,
                         const float* __restrict__ wq, const float* __restrict__ wk,
                         const float* __restrict__ wv, const float* __restrict__ bq,
                         const float* __restrict__ bk, const float* __restrict__ bv,
                         __half* __restrict__ W1, __half* __restrict__ W2,
                         __half* __restrict__ Wp, __half* __restrict__ Wff,
                         __half* __restrict__ Wqkv, float* __restrict__ Bqkv) {
    int idx = blockIdx.x * 256 + threadIdx.x;
    if (idx < 320) g_bst[idx] = 0.0f;
    if (idx < 4096) g_tacc[idx] = 0.0f;
    if (idx < 262144) {
        W1[idx] = __float2half_rn(pw1[idx]);
    } else if (idx < 524288) {
        int o = idx - 262144; W2[o] = __float2half_rn(pw2[o]);
    } else if (idx < 786432) {
        int o = idx - 524288; Wp[o] = __float2half_rn(wp[o]);
    } else if (idx < 1048576) {
        int o = idx - 786432; Wff[o] = __float2half_rn(ffw[o]);
    } else {
        int o2 = idx - 1048576;           // 0..786431
        int sel = o2 >> 18;
        int off = o2 & 262143;
        const float* src = (sel == 0) ? wq : ((sel == 1) ? wk : wv);
        Wqkv[o2] = __float2half_rn(src[off]);
        if (off < 512) {
            const float* bs = (sel == 0) ? bq : ((sel == 1) ? bk : bv);
            Bqkv[sel * 512 + off] = bs[off];
        }
    }
}

// ---------------- input transpose + positional encoding + batch stats ------
__global__ void k_transpose_in(const float* __restrict__ in, float* __restrict__ X) {
    __shared__ float tile[32][33];
    __shared__ float rs[256], rq[256];
    int b = blockIdx.z;
    int t0 = blockIdx.x * 32, c0 = blockIdx.y * 32;
    int tx = threadIdx.x, ty = threadIdx.y;
    #pragma unroll
    for (int i = ty; i < 32; i += 8)
        tile[i][tx] = in[((size_t)b * TT + t0 + i) * CC + c0 + tx];
    __syncthreads();
    float s = 0.0f, q = 0.0f;
    #pragma unroll
    for (int i = ty; i < 32; i += 8) {
        int c = c0 + i;
        float div = expf((float)(c & ~1) * (-9.210340371976184f / 512.0f));
        float ang = (float)b * div;
        float pe = (c & 1) ? cosf(ang) : sinf(ang);
        float v = tile[tx][i] + pe;
        X[((size_t)c * BB + b) * TT + t0 + tx] = v;
        s += v; q += v * v;
    }
    int tid = ty * 32 + tx;
    rs[tid] = s; rq[tid] = q;
    __syncthreads();
    for (int o = 128; o > 0; o >>= 1) {
        if (tid < o) { rs[tid] += rs[tid + o]; rq[tid] += rq[tid + o]; }
        __syncthreads();
    }
    if (tid == 0) {
        atomicAdd(&g_bst[2 * b], rs[0]);
        atomicAdd(&g_bst[2 * b + 1], rq[0]);
    }
}

// ---------------- finalize per-t stats (single launch, no re-zero) ---------
__global__ void k_tfinal() {
    int t = blockIdx.x * 256 + threadIdx.x;
    float s = g_tacc[2 * t], q = g_tacc[2 * t + 1];
    float mu = s * (1.0f / 16384.0f);
    float var = q * (1.0f / 16384.0f) - mu * mu;
    g_tmean[t] = mu;
    g_trstd[t] = rsqrtf(var + (float)EPS);
}

// ---------------- fused per-batch-LN + depthwise conv (k=7) -> fp16 --------
// Stats finalized inline from staged raw sums (thread 0, shared broadcast).
__global__ void k_dwconv(const float* __restrict__ X, const float* __restrict__ dww,
                         const float* __restrict__ dwb, __half* __restrict__ D,
                         const float* __restrict__ bst) {
    int c = blockIdx.x, b = blockIdx.y;
    int tid = threadIdx.x;
    __shared__ float s[TT + 16];   // x[t] at s[t+4]
    __shared__ float s_mu, s_r;
    const float4* row4 = (const float4*)(X + ((size_t)c * BB + b) * TT);
    float4 v0 = row4[tid];
    float4 v1 = row4[tid + 256];
    if (tid == 0) {
        float sum = bst[2 * b], sq = bst[2 * b + 1];
        float mu = sum * INV_BN;
        float var = sq * INV_BN - mu * mu;
        s_mu = mu;
        s_r = rsqrtf(var + (float)EPS);
    }
    __syncthreads();
    float mu = s_mu, r = s_r;
    v0.x = (v0.x - mu) * r; v0.y = (v0.y - mu) * r;
    v0.z = (v0.z - mu) * r; v0.w = (v0.w - mu) * r;
    v1.x = (v1.x - mu) * r; v1.y = (v1.y - mu) * r;
    v1.z = (v1.z - mu) * r; v1.w = (v1.w - mu) * r;
    *(float4*)&s[4 + tid * 4] = v0;
    *(float4*)&s[4 + (tid + 256) * 4] = v1;
    if (tid < 4) s[tid] = 0.0f;
    else if (tid < 8) s[2048 + tid] = 0.0f;
    __syncthreads();
    float w0 = dww[c * 7 + 0], w1 = dww[c * 7 + 1], w2 = dww[c * 7 + 2], w3 = dww[c * 7 + 3];
    float w4 = dww[c * 7 + 4], w5 = dww[c * 7 + 5], w6 = dww[c * 7 + 6];
    float bias = dwb[c];
    int t0 = tid * 8;
    float xv[16];
    *(float4*)&xv[0]  = *(const float4*)&s[t0];
    *(float4*)&xv[4]  = *(const float4*)&s[t0 + 4];
    *(float4*)&xv[8]  = *(const float4*)&s[t0 + 8];
    *(float4*)&xv[12] = *(const float4*)&s[t0 + 12];
    __half2 oh[4];
    #pragma unroll
    for (int j = 0; j < 8; j += 2) {
        float a0 = bias, a1 = bias;
        a0 += w0 * xv[j + 1]; a1 += w0 * xv[j + 2];
        a0 += w1 * xv[j + 2]; a1 += w1 * xv[j + 3];
        a0 += w2 * xv[j + 3]; a1 += w2 * xv[j + 4];
        a0 += w3 * xv[j + 4]; a1 += w3 * xv[j + 5];
        a0 += w4 * xv[j + 5]; a1 += w4 * xv[j + 6];
        a0 += w5 * xv[j + 6]; a1 += w5 * xv[j + 7];
        a0 += w6 * xv[j + 7]; a1 += w6 * xv[j + 8];
        oh[j >> 1] = __halves2half2(__float2half_rn(a0), __float2half_rn(a1));
    }
    uint4 wv = { *(uint32_t*)&oh[0], *(uint32_t*)&oh[1], *(uint32_t*)&oh[2], *(uint32_t*)&oh[3] };
    *(uint4*)(D + ((size_t)c * BB + b) * TT + t0) = wv;
}

// ---------------- elementwise LN + fp32->fp16 (layout preserved) -----------
// MODE 1: per-batch LN (inline finalize from bst; one b per block);
// MODE 2: per-t LN (uses g_tmean/g_trstd from k_tfinal)
template <int MODE>
__global__ void k_cvtBe(const float* __restrict__ X, __half* __restrict__ Bt,
                        const float* __restrict__ bst) {
    __shared__ float s_mu, s_r;
    size_t i = ((size_t)blockIdx.x * 256 + threadIdx.x) * 4;
    if (MODE == 1) {
        if (threadIdx.x == 0) {
            int b = (int)((i >> 11) & 31);   // single b per block (1024-elem window)
            float sum = bst[2 * b], sq = bst[2 * b + 1];
            float mu = sum * INV_BN;
            float var = sq * INV_BN - mu * mu;
            s_mu = mu;
            s_r = rsqrtf(var + (float)EPS);
        }
        __syncthreads();
    }
    float4 v = *(const float4*)&X[i];
    if (MODE == 1) {
        float mu = s_mu, sc = s_r;
        v.x = (v.x - mu) * sc; v.y = (v.y - mu) * sc;
        v.z = (v.z - mu) * sc; v.w = (v.w - mu) * sc;
    } else {
        int t0 = (int)(i & (TT - 1));
        float4 m = *(const float4*)&g_tmean[t0];
        float4 r = *(const float4*)&g_trstd[t0];
        v.x = (v.x - m.x) * r.x; v.y = (v.y - m.y) * r.y;
        v.z = (v.z - m.z) * r.z; v.w = (v.w - m.w) * r.w;
    }
    __half2 h0 = __halves2half2(__float2half_rn(v.x), __float2half_rn(v.y));
    __half2 h1 = __halves2half2(__float2half_rn(v.z), __float2half_rn(v.w));
    uint2 w = { *(uint32_t*)&h0, *(uint32_t*)&h1 };
    *(uint2*)&Bt[i] = w;
}

// ---------------- tensor-core GEMM: C[M,65536] (+)= W @ X + bias ------------
// A fp16 [M][512] row-major; B fp16 [512][65536] K-major.
// CTA 128x128, 8 warps (warp 64x32), K chunks of 64, 3-stage cp.async.
// Mainloop: 1 sync per chunk; B fragments double-buffered across kk (r9 best).
// STATS: 0 none, 1 per-batch raw sums -> bstat, 2 per-t -> g_tacc.
#define KSTAGE 64
#define NSTG 3
#define A_BYTES 16384
#define STG_BYTES 32768
#define MMA_SMEM (NSTG * STG_BYTES)
#define NKC 8

template <int BETA, int STATS, int TRANS, typename OutT>
__global__ void __launch_bounds__(256, 2)
k_mma(const __half* __restrict__ Wb, const __half* __restrict__ Bt,
      const float* __restrict__ bias, OutT* __restrict__ C, const float* __restrict__ Cin,
      float* __restrict__ bstat) {
    extern __shared__ char dsm[];
    uint32_t smb = smem_u32(dsm);
    int tid = threadIdx.x;
    int wid = tid >> 5, lane = tid & 31;
    int m0 = blockIdx.x * 128, n0 = blockIdx.y * 128;
    int warp_m = wid >> 2, warp_n = wid & 3;

    float acc[4][4][4];
    #pragma unroll
    for (int a = 0; a < 4; a++)
        #pragma unroll
        for (int b = 0; b < 4; b++)
            #pragma unroll
            for (int c = 0; c < 4; c++) acc[a][b][c] = 0.0f;

    int arow = tid >> 3, ach = tid & 7;
    int brow = tid >> 4, bch = tid & 15;

    auto prefetch = [&](int st, int kc) {
        uint32_t sA = smb + st * STG_BYTES;
        uint32_t sB = sA + A_BYTES;
        #pragma unroll
        for (int i = 0; i < 4; i++) {
            int row = arow + i * 32;
            const __half* g = Wb + (size_t)(m0 + row) * 512 + kc * KSTAGE + ach * 8;
            cp_async16(sA + row * 128 + ((ach ^ (row & 7)) << 4), g);
        }
        #pragma unroll
        for (int i = 0; i < 4; i++) {
            int row = brow + i * 16;
            const __half* g = Bt + (size_t)(kc * KSTAGE + row) * NN + n0 + bch * 8;
            cp_async16(sB + row * 256 + ((bch ^ (row & 7)) << 4), g);
        }
    };

    prefetch(0, 0); CP_COMMIT();
    prefetch(1, 1); CP_COMMIT();

    int lr = lane & 7, lq = lane >> 3;
    int rowoff = lr + (lq & 1) * 8;
    int csel = lq >> 1;
    int bk_off = (lq & 1) * 8 + lr;
    int bn_half = lq >> 1;

    for (int i = 0; i < NKC; i++) {
        CP_WAIT1();
        __syncthreads();
        if (i + 2 < NKC) prefetch((i + 2) % NSTG, i + 2);
        CP_COMMIT();

        uint32_t sA = smb + (i % NSTG) * STG_BYTES;
        uint32_t sB = sA + A_BYTES;

        uint32_t bf[2][2][4];
        // preload B fragments for kk = 0
        #pragma unroll
        for (int nf = 0; nf < 2; nf++) {
            int krow = bk_off;
            int nch = warp_n * 4 + nf * 2 + bn_half;
            ldmatrix_x4_trans(bf[0][nf][0], bf[0][nf][1], bf[0][nf][2], bf[0][nf][3],
                              sB + krow * 256 + ((nch ^ (krow & 7)) << 4));
        }
        #pragma unroll
        for (int kk = 0; kk < 4; kk++) {
            int cur = kk & 1;
            if (kk < 3) {   // prefetch B fragments of kk+1 into the other buffer
                #pragma unroll
                for (int nf = 0; nf < 2; nf++) {
                    int krow = (kk + 1) * 16 + bk_off;
                    int nch = warp_n * 4 + nf * 2 + bn_half;
                    ldmatrix_x4_trans(bf[cur ^ 1][nf][0], bf[cur ^ 1][nf][1],
                                      bf[cur ^ 1][nf][2], bf[cur ^ 1][nf][3],
                                      sB + krow * 256 + ((nch ^ (krow & 7)) << 4));
                }
            }
            int chnk = kk * 2 + csel;
            uint32_t af[4][4];
            #pragma unroll
            for (int mf = 0; mf < 4; mf++) {
                int row = warp_m * 64 + mf * 16 + rowoff;
                ldmatrix_x4(af[mf][0], af[mf][1], af[mf][2], af[mf][3],
                            sA + row * 128 + ((chnk ^ (row & 7)) << 4));
            }
            #pragma unroll
            for (int mf = 0; mf < 4; mf++)
                #pragma unroll
                for (int t = 0; t < 4; t++)
                    mma16816(acc[mf][t], af[mf],
                             bf[cur][t >> 1][(t & 1) * 2], bf[cur][t >> 1][(t & 1) * 2 + 1]);
        }
        // no trailing sync: leading sync of next iter protects stage reuse
    }
    __syncthreads();   // all mainloop SMEM reads done before epilogue reuses dsm

    // ---- epilogue ----
    float* colsum = (float*)dsm;        // STATS==2: [128] + [128]
    float* colsq  = colsum + 128;
    float* stg    = (float*)dsm;        // TRANS: [128][132]
    if (STATS == 2) {
        if (tid < 128) { colsum[tid] = 0.0f; colsq[tid] = 0.0f; }
        __syncthreads();
    }
    float s_part = 0.0f, q_part = 0.0f;
    int g = lane >> 2, tg = lane & 3;
    #pragma unroll
    for (int mf = 0; mf < 4; mf++) {
        int mlA = warp_m * 64 + mf * 16 + g;
        int mlB = mlA + 8;
        int mA = m0 + mlA, mB2 = m0 + mlB;
        float bva = bias[mA], bvb = bias[mB2];
        #pragma unroll
        for (int t = 0; t < 4; t++) {
            int nl = warp_n * 32 + t * 8 + tg * 2;
            int n = n0 + nl;
            size_t o0 = (size_t)mA * NN + n;
            size_t o1 = (size_t)mB2 * NN + n;
            float v00 = acc[mf][t][0] + bva, v01 = acc[mf][t][1] + bva;
            float v10 = acc[mf][t][2] + bvb, v11 = acc[mf][t][3] + bvb;
            if (BETA) {
                float2 p0 = *(const float2*)&Cin[o0];
                float2 p1 = *(const float2*)&Cin[o1];
                v00 += p0.x; v01 += p0.y;
                v10 += p1.x; v11 += p1.y;
            }
            if (STATS == 1) {
                s_part += v00 + v01 + v10 + v11;
                q_part += v00 * v00 + v01 * v01 + v10 * v10 + v11 * v11;
            }
            if (STATS == 2) {
                atomicAdd(&colsum[nl], v00 + v10);
                atomicAdd(&colsum[nl + 1], v01 + v11);
                atomicAdd(&colsq[nl], v00 * v00 + v10 * v10);
                atomicAdd(&colsq[nl + 1], v01 * v01 + v11 * v11);
            }
            if (TRANS) {
                stg[nl * 132 + mlA] = v00;
                stg[(nl + 1) * 132 + mlA] = v01;
                stg[nl * 132 + mlB] = v10;
                stg[(nl + 1) * 132 + mlB] = v11;
            } else if (sizeof(OutT) == 4) {
                float2 w0 = { v00, v01 }, w1 = { v10, v11 };
                *(float2*)&((float*)C)[o0] = w0;
                *(float2*)&((float*)C)[o1] = w1;
            } else {
                __half2 h0 = __halves2half2(__float2half_rn(v00), __float2half_rn(v01));
                __half2 h1 = __halves2half2(__float2half_rn(v10), __float2half_rn(v11));
                *(uint32_t*)&((__half*)C)[o0] = *(uint32_t*)&h0;
                *(uint32_t*)&((__half*)C)[o1] = *(uint32_t*)&h1;
            }
        }
    }
    if (STATS == 1) {
        float* red = (float*)dsm;
        red[tid] = s_part; red[256 + tid] = q_part;
        __syncthreads();
        for (int o = 128; o > 0; o >>= 1) {
            if (tid < o) { red[tid] += red[tid + o]; red[256 + tid] += red[256 + tid + o]; }
            __syncthreads();
        }
        if (tid == 0) {
            int b = n0 >> 11;
            atomicAdd(&bstat[2 * b], red[0]);
            atomicAdd(&bstat[2 * b + 1], red[256]);
        }
    }
    if (STATS == 2) {
        __syncthreads();
        if (tid < 128) {
            int t = (n0 + tid) & (TT - 1);
            atomicAdd(&g_tacc[2 * t], colsum[tid]);
            atomicAdd(&g_tacc[2 * t + 1], colsq[tid]);
        }
    }
    if (TRANS) {
        __syncthreads();
        int ml = tid & 127;
        for (int nl = tid >> 7; nl < 128; nl += 2)
            ((float*)C)[(size_t)(n0 + nl) * CC + m0 + ml] = stg[nl * 132 + ml];
    }
}

// ---------------- attention over the batch axis (fp16 QKV in, fp16 out) ----
#define AT 8
#define SQ_OFF 0
#define SK_OFF 16384
#define SV_OFF 32768
#define ST_OFF 51200
#define ATTN_SMEM_FLOATS (16384 + 16384 + 18432 + 1056)
#define ATTN_SMEM_BYTES (ATTN_SMEM_FLOATS * 4)

__global__ void k_attn(const __half* __restrict__ QKV, __half* __restrict__ O) {
    extern __shared__ float sm[];
    float* smq = sm + SQ_OFF;
    float* smk = sm + SK_OFF;
    float* smv = sm + SV_OFF;
    float* st  = sm + ST_OFF;
    int h = blockIdx.y;
    int t0 = blockIdx.x * AT;
    int tid = threadIdx.x;

    const __half* Qh = QKV;
    const __half* Kh = QKV + (size_t)512 * NN;
    const __half* Vh = QKV + (size_t)1024 * NN;

    for (int p0 = tid; p0 < 2048; p0 += 256) {
        int d = p0 >> 5, b = p0 & 31;
        size_t base = ((size_t)(h * 64 + d) * 32 + b) * 2048 + t0;
        uint4 qr = *(const uint4*)&Qh[base];
        uint4 kr = *(const uint4*)&Kh[base];
        uint4 vr = *(const uint4*)&Vh[base];
        __half2* qh = (__half2*)&qr;
        __half2* kh = (__half2*)&kr;
        __half2* vh = (__half2*)&vr;
        #pragma unroll
        for (int j = 0; j < 4; j++) {
            float2 qf = __half22float2(qh[j]);
            float2 kf = __half22float2(kh[j]);
            float2 vf = __half22float2(vh[j]);
            smq[((2 * j) * 64 + d) * 32 + b] = qf.x;
            smq[((2 * j + 1) * 64 + d) * 32 + b] = qf.y;
            smk[((2 * j) * 64 + d) * 32 + b] = kf.x;
            smk[((2 * j + 1) * 64 + d) * 32 + b] = kf.y;
            smv[((2 * j) * 64 + d) * 36 + b] = vf.x;
            smv[((2 * j + 1) * 64 + d) * 36 + b] = vf.y;
        }
    }
    __syncthreads();

    const float scale = 0.125f;
    int sb = tid >> 3, sp0 = (tid & 7) * 4;
    for (int ttk = 0; ttk < AT; ttk++) {
        float a0 = 0, a1 = 0, a2 = 0, a3 = 0;
        #pragma unroll
        for (int d = 0; d < 64; d++) {
            float qv = smq[(ttk * 64 + d) * 32 + sb];
            float4 kv = *(const float4*)&smk[(ttk * 64 + d) * 32 + sp0];
            a0 += qv * kv.x; a1 += qv * kv.y; a2 += qv * kv.z; a3 += qv * kv.w;
        }
        st[sb * 33 + sp0 + 0] = a0 * scale;
        st[sb * 33 + sp0 + 1] = a1 * scale;
        st[sb * 33 + sp0 + 2] = a2 * scale;
        st[sb * 33 + sp0 + 3] = a3 * scale;
        __syncthreads();
        if (tid < 32) {
            const float* row = st + tid * 33;
            float mx = -1e30f;
            #pragma unroll
            for (int j = 0; j < 32; j++) mx = fmaxf(mx, row[j]);
            float ev[32]; float sum = 0.0f;
            #pragma unroll
            for (int j = 0; j < 32; j++) { ev[j] = expf(row[j] - mx); sum += ev[j]; }
            float inv = 1.0f / sum;
            #pragma unroll
            for (int j = 0; j < 32; j++) smq[ttk * 1152 + tid * 36 + j] = ev[j] * inv;
        }
        __syncthreads();
    }

    for (int rep = 0; rep < 8; rep++) {
        int o = tid + rep * 256;
        int ob = o >> 6, od = o & 63;
        float outv[8];
        #pragma unroll
        for (int s = 0; s < 8; s++) {
            float acc = 0.0f;
            #pragma unroll
            for (int bp = 0; bp < 32; bp += 4) {
                float4 pv = *(const float4*)&smq[s * 1152 + ob * 36 + bp];
                float4 vv = *(const float4*)&smv[(s * 64 + od) * 36 + bp];
                acc += pv.x * vv.x + pv.y * vv.y + pv.z * vv.z + pv.w * vv.w;
            }
            outv[s] = acc;
        }
        size_t base = ((size_t)(h * 64 + od) * 32 + ob) * 2048 + t0;
        __half2 h0 = __halves2half2(__float2half_rn(outv[0]), __float2half_rn(outv[1]));
        __half2 h1 = __halves2half2(__float2half_rn(outv[2]), __float2half_rn(outv[3]));
        __half2 h2 = __halves2half2(__float2half_rn(outv[4]), __float2half_rn(outv[5]));
        __half2 h3 = __halves2half2(__float2half_rn(outv[6]), __float2half_rn(outv[7]));
        uint4 w = { *(uint32_t*)&h0, *(uint32_t*)&h1, *(uint32_t*)&h2, *(uint32_t*)&h3 };
        *(uint4*)&O[base] = w;
    }
}

// ---------------- launch --------------------------------------------------
extern "C" void kernel_launch(void* const* d_in, const int* in_sizes, int n_in,
                              void* d_out, int out_size) {
    const float* x     = (const float*)d_in[0];
    const float* dw1_w = (const float*)d_in[1];
    const float* dw1_b = (const float*)d_in[2];
    const float* pw1_w = (const float*)d_in[3];
    const float* pw1_b = (const float*)d_in[4];
    const float* dw2_w = (const float*)d_in[5];
    const float* dw2_b = (const float*)d_in[6];
    const float* pw2_w = (const float*)d_in[7];
    const float* pw2_b = (const float*)d_in[8];
    const float* wq = (const float*)d_in[9];
    const float* bq = (const float*)d_in[10];
    const float* wk = (const float*)d_in[11];
    const float* bk = (const float*)d_in[12];
    const float* wv = (const float*)d_in[13];
    const float* bv = (const float*)d_in[14];
    const float* wp = (const float*)d_in[15];
    const float* bp = (const float*)d_in[16];
    const float* ff_w = (const float*)d_in[17];
    const float* ff_b = (const float*)d_in[18];
    float* out = (float*)d_out;

    float *pX, *pBqkv, *pBst;
    __half *pBt, *pQKV, *pWb, *pWb2, *pWp, *pWff, *pWqkv;
    cudaGetSymbolAddress((void**)&pX, gX);
    cudaGetSymbolAddress((void**)&pBt, gBt);
    cudaGetSymbolAddress((void**)&pQKV, gQKV);
    cudaGetSymbolAddress((void**)&pWb, gWb);
    cudaGetSymbolAddress((void**)&pWb2, gWb2);
    cudaGetSymbolAddress((void**)&pWp, gWp);
    cudaGetSymbolAddress((void**)&pWff, gWff);
    cudaGetSymbolAddress((void**)&pWqkv, gWqkv);
    cudaGetSymbolAddress((void**)&pBqkv, gBqkv);
    cudaGetSymbolAddress((void**)&pBst, g_bst);

    cudaFuncSetAttribute(k_attn, cudaFuncAttributeMaxDynamicSharedMemorySize, ATTN_SMEM_BYTES);
    cudaFuncSetAttribute((k_mma<0, 1, 0, float>), cudaFuncAttributeMaxDynamicSharedMemorySize, MMA_SMEM);
    cudaFuncSetAttribute((k_mma<1, 1, 0, float>), cudaFuncAttributeMaxDynamicSharedMemorySize, MMA_SMEM);
    cudaFuncSetAttribute((k_mma<0, 0, 0, __half>), cudaFuncAttributeMaxDynamicSharedMemorySize, MMA_SMEM);
    cudaFuncSetAttribute((k_mma<1, 2, 0, float>), cudaFuncAttributeMaxDynamicSharedMemorySize, MMA_SMEM);
    cudaFuncSetAttribute((k_mma<1, 0, 1, float>), cudaFuncAttributeMaxDynamicSharedMemorySize, MMA_SMEM);

    dim3 mmaG(4, 512);       // m fast -> B tiles shared across m via L2
    dim3 mmaGqkv(12, 512);

    // 0) weight converts + stat zeroing; input transpose + pos-enc (+stats -> stage 0)
    k_cvtall<<<7168, 256>>>(pw1_w, pw2_w, wp, ff_w, wq, wk, wv, bq, bk, bv,
                            pWb, pWb2, pWp, pWff, pWqkv, pBqkv);
    k_transpose_in<<<dim3(TT / 32, CC / 32, BB), dim3(32, 8)>>>(x, pX);

    // 1) conv block 1: X = pw1 @ dwconv1(LN_b(X)) + b   (stats stage 0 -> 1)
    k_dwconv<<<dim3(CC, BB), 256>>>(pX, dw1_w, dw1_b, pBt, pBst);
    k_mma<0, 1, 0, float><<<mmaG, 256, MMA_SMEM>>>(pWb, pBt, pw1_b, pX, pX, pBst + 64);

    // 2) conv blocks 2..4 (shared weights), stats stages 1->2->3->4
    for (int it = 0; it < 3; it++) {
        k_dwconv<<<dim3(CC, BB), 256>>>(pX, dw2_w, dw2_b, pBt, pBst + (it + 1) * 64);
        k_mma<1, 1, 0, float><<<mmaG, 256, MMA_SMEM>>>(pWb2, pBt, pw2_b, pX, pX,
                                                       pBst + (it + 2) * 64);
    }

    // 3) attention over batch axis (merged QKV GEMM, fp16); LN from stage 4
    k_cvtBe<1><<<32768, 256>>>(pX, pBt, pBst + 4 * 64);
    k_mma<0, 0, 0, __half><<<mmaGqkv, 256, MMA_SMEM>>>(pWqkv, pBt, pBqkv, pQKV,
                                                       (const float*)0, (float*)0);
    k_attn<<<dim3(TT / AT, HH), 256, ATTN_SMEM_BYTES>>>(pQKV, pBt);
    k_mma<1, 2, 0, float><<<mmaG, 256, MMA_SMEM>>>(pWp, pBt, bp, pX, pX, (float*)0);
    k_tfinal<<<TT / 256, 256>>>();

    // 4) FF with per-t LN; final GEMM writes output transposed (B,T,F)
    k_cvtBe<2><<<32768, 256>>>(pX, pBt, (const float*)0);
    k_mma<1, 0, 1, float><<<mmaG, 256, MMA_SMEM>>>(pWff, pBt, ff_b, out, pX, (float*)0);

    (void)in_sizes; (void)n_in; (void)out_size;
}

// round 14
// speedup vs baseline: 1.1553x; 1.0211x over previous
#include <cuda_runtime.h>
#include <cuda_fp16.h>
#include <cstdint>
#include <math.h>

// ---------------- problem constants ----------------
#define BB 32
#define TT 2048
#define CC 512          // E == F == 512
#define NN 65536        // B*T
#define HH 8
#define EPS 1e-5
#define INV_BN 9.5367431640625e-7f    // 1/1048576

// ---------------- scratch (device globals; allocation-free rule) ----------
__device__ float gX[33554432];     // state, layout (C, B, T) fp32
__device__ __half gBt[33554432];   // GEMM B operand, K-major [512][65536] fp16
__device__ __half gQKV[100663296]; // merged QKV output fp16 [1536][65536]
__device__ __half gWb[262144];     // pw1 weights fp16
__device__ __half gWb2[262144];    // pw2 weights fp16
__device__ __half gWp[262144];     // wp weights fp16
__device__ __half gWff[262144];    // ff weights fp16
__device__ __half gWqkv[786432];   // merged q|k|v weights fp16 [1536][512]
__device__ float gBqkv[1536];      // merged q|k|v bias

__device__ float g_bst[5 * 64];    // staged per-batch (sum, sumsq): 5 stages x 32 b
__device__ float g_tacc[4096];     // per-t (sum, sumsq)
__device__ float g_tmean[2048], g_trstd[2048];

// ================= helpers =================
__device__ __forceinline__ uint32_t smem_u32(const void* p) {
    uint32_t a;
    asm("{ .reg .u64 t; cvta.to.shared.u64 t, %1; cvt.u32.u64 %0, t; }" : "=r"(a) : "l"(p));
    return a;
}
__device__ __forceinline__ void cp_async16(uint32_t smaddr, const void* g) {
    asm volatile("cp.async.cg.shared.global [%0], [%1], 16;" :: "r"(smaddr), "l"(g));
}
#define CP_COMMIT() asm volatile("cp.async.commit_group;" ::: "memory")
#define CP_WAIT1()  asm volatile("cp.async.wait_group 1;" ::: "memory")

__device__ __forceinline__ void ldmatrix_x4(uint32_t& r0, uint32_t& r1, uint32_t& r2,
                                            uint32_t& r3, uint32_t addr) {
    asm volatile("ldmatrix.sync.aligned.m8n8.x4.shared.b16 {%0,%1,%2,%3}, [%4];"
        : "=r"(r0), "=r"(r1), "=r"(r2), "=r"(r3) : "r"(addr));
}
__device__ __forceinline__ void ldmatrix_x4_trans(uint32_t& r0, uint32_t& r1, uint32_t& r2,
                                                  uint32_t& r3, uint32_t addr) {
    asm volatile("ldmatrix.sync.aligned.m8n8.x4.trans.shared.b16 {%0,%1,%2,%3}, [%4];"
        : "=r"(r0), "=r"(r1), "=r"(r2), "=r"(r3) : "r"(addr));
}
__device__ __forceinline__ void mma16816(float* d, const uint32_t* a, uint32_t b0, uint32_t b1) {
    asm volatile(
        "mma.sync.aligned.m16n8k16.row.col.f32.f16.f16.f32 "
        "{%0,%1,%2,%3}, {%4,%5,%6,%7}, {%8,%9}, {%0,%1,%2,%3};"
        : "+f"(d[0]), "+f"(d[1]), "+f"(d[2]), "+f"(d[3])
        : "r"(a[0]), "r"(a[1]), "r"(a[2]), "r"(a[3]), "r"(b0), "r"(b1));
}

// ---------------- all weight converts + qkv pack + stat zeroing ------------
__global__ void k_cvtall(const float* __restrict__ pw1, const float* __restrict__ pw2,
                         const float* __restrict__ wp, const float* __restrict__ ffw,
                         const float* __restrict__ wq, const float* __restrict__ wk,
                         const float* __restrict__ wv, const float* __restrict__ bq,
                         const float* __restrict__ bk, const float* __restrict__ bv,
                         __half* __restrict__ W1, __half* __restrict__ W2,
                         __half* __restrict__ Wp, __half* __restrict__ Wff,
                         __half* __restrict__ Wqkv, float* __restrict__ Bqkv) {
    int idx = blockIdx.x * 256 + threadIdx.x;
    if (idx < 320) g_bst[idx] = 0.0f;
    if (idx < 4096) g_tacc[idx] = 0.0f;
    if (idx < 262144) {
        W1[idx] = __float2half_rn(pw1[idx]);
    } else if (idx < 524288) {
        int o = idx - 262144; W2[o] = __float2half_rn(pw2[o]);
    } else if (idx < 786432) {
        int o = idx - 524288; Wp[o] = __float2half_rn(wp[o]);
    } else if (idx < 1048576) {
        int o = idx - 786432; Wff[o] = __float2half_rn(ffw[o]);
    } else {
        int o2 = idx - 1048576;           // 0..786431
        int sel = o2 >> 18;
        int off = o2 & 262143;
        const float* src = (sel == 0) ? wq : ((sel == 1) ? wk : wv);
        Wqkv[o2] = __float2half_rn(src[off]);
        if (off < 512) {
            const float* bs = (sel == 0) ? bq : ((sel == 1) ? bk : bv);
            Bqkv[sel * 512 + off] = bs[off];
        }
    }
}

// ---------------- input transpose + positional encoding + batch stats ------
__global__ void k_transpose_in(const float* __restrict__ in, float* __restrict__ X) {
    __shared__ float tile[32][33];
    __shared__ float rs[256], rq[256];
    int b = blockIdx.z;
    int t0 = blockIdx.x * 32, c0 = blockIdx.y * 32;
    int tx = threadIdx.x, ty = threadIdx.y;
    #pragma unroll
    for (int i = ty; i < 32; i += 8)
        tile[i][tx] = in[((size_t)b * TT + t0 + i) * CC + c0 + tx];
    __syncthreads();
    float s = 0.0f, q = 0.0f;
    #pragma unroll
    for (int i = ty; i < 32; i += 8) {
        int c = c0 + i;
        float div = expf((float)(c & ~1) * (-9.210340371976184f / 512.0f));
        float ang = (float)b * div;
        float pe = (c & 1) ? cosf(ang) : sinf(ang);
        float v = tile[tx][i] + pe;
        X[((size_t)c * BB + b) * TT + t0 + tx] = v;
        s += v; q += v * v;
    }
    int tid = ty * 32 + tx;
    rs[tid] = s; rq[tid] = q;
    __syncthreads();
    for (int o = 128; o > 0; o >>= 1) {
        if (tid < o) { rs[tid] += rs[tid + o]; rq[tid] += rq[tid + o]; }
        __syncthreads();
    }
    if (tid == 0) {
        atomicAdd(&g_bst[2 * b], rs[0]);
        atomicAdd(&g_bst[2 * b + 1], rq[0]);
    }
}

// ---------------- finalize per-t stats (single launch) ---------------------
__global__ void k_tfinal() {
    int t = blockIdx.x * 256 + threadIdx.x;
    float s = g_tacc[2 * t], q = g_tacc[2 * t + 1];
    float mu = s * (1.0f / 16384.0f);
    float var = q * (1.0f / 16384.0f) - mu * mu;
    g_tmean[t] = mu;
    g_trstd[t] = rsqrtf(var + (float)EPS);
}

// ---------------- fused per-batch-LN + depthwise conv (k=7) -> fp16 --------
__global__ void k_dwconv(const float* __restrict__ X, const float* __restrict__ dww,
                         const float* __restrict__ dwb, __half* __restrict__ D,
                         const float* __restrict__ bst) {
    int c = blockIdx.x, b = blockIdx.y;
    int tid = threadIdx.x;
    __shared__ float s[TT + 16];   // x[t] at s[t+4]
    __shared__ float s_mu, s_r;
    const float4* row4 = (const float4*)(X + ((size_t)c * BB + b) * TT);
    float4 v0 = row4[tid];
    float4 v1 = row4[tid + 256];
    if (tid == 0) {
        float sum = bst[2 * b], sq = bst[2 * b + 1];
        float mu = sum * INV_BN;
        float var = sq * INV_BN - mu * mu;
        s_mu = mu;
        s_r = rsqrtf(var + (float)EPS);
    }
    __syncthreads();
    float mu = s_mu, r = s_r;
    v0.x = (v0.x - mu) * r; v0.y = (v0.y - mu) * r;
    v0.z = (v0.z - mu) * r; v0.w = (v0.w - mu) * r;
    v1.x = (v1.x - mu) * r; v1.y = (v1.y - mu) * r;
    v1.z = (v1.z - mu) * r; v1.w = (v1.w - mu) * r;
    *(float4*)&s[4 + tid * 4] = v0;
    *(float4*)&s[4 + (tid + 256) * 4] = v1;
    if (tid < 4) s[tid] = 0.0f;
    else if (tid < 8) s[2048 + tid] = 0.0f;
    __syncthreads();
    float w0 = dww[c * 7 + 0], w1 = dww[c * 7 + 1], w2 = dww[c * 7 + 2], w3 = dww[c * 7 + 3];
    float w4 = dww[c * 7 + 4], w5 = dww[c * 7 + 5], w6 = dww[c * 7 + 6];
    float bias = dwb[c];
    int t0 = tid * 8;
    float xv[16];
    *(float4*)&xv[0]  = *(const float4*)&s[t0];
    *(float4*)&xv[4]  = *(const float4*)&s[t0 + 4];
    *(float4*)&xv[8]  = *(const float4*)&s[t0 + 8];
    *(float4*)&xv[12] = *(const float4*)&s[t0 + 12];
    __half2 oh[4];
    #pragma unroll
    for (int j = 0; j < 8; j += 2) {
        float a0 = bias, a1 = bias;
        a0 += w0 * xv[j + 1]; a1 += w0 * xv[j + 2];
        a0 += w1 * xv[j + 2]; a1 += w1 * xv[j + 3];
        a0 += w2 * xv[j + 3]; a1 += w2 * xv[j + 4];
        a0 += w3 * xv[j + 4]; a1 += w3 * xv[j + 5];
        a0 += w4 * xv[j + 5]; a1 += w4 * xv[j + 6];
        a0 += w5 * xv[j + 6]; a1 += w5 * xv[j + 7];
        a0 += w6 * xv[j + 7]; a1 += w6 * xv[j + 8];
        oh[j >> 1] = __halves2half2(__float2half_rn(a0), __float2half_rn(a1));
    }
    uint4 wv = { *(uint32_t*)&oh[0], *(uint32_t*)&oh[1], *(uint32_t*)&oh[2], *(uint32_t*)&oh[3] };
    *(uint4*)(D + ((size_t)c * BB + b) * TT + t0) = wv;
}

// ---------------- elementwise LN + fp32->fp16 (layout preserved) -----------
template <int MODE>
__global__ void k_cvtBe(const float* __restrict__ X, __half* __restrict__ Bt,
                        const float* __restrict__ bst) {
    __shared__ float s_mu, s_r;
    size_t i = ((size_t)blockIdx.x * 256 + threadIdx.x) * 4;
    if (MODE == 1) {
        if (threadIdx.x == 0) {
            int b = (int)((i >> 11) & 31);
            float sum = bst[2 * b], sq = bst[2 * b + 1];
            float mu = sum * INV_BN;
            float var = sq * INV_BN - mu * mu;
            s_mu = mu;
            s_r = rsqrtf(var + (float)EPS);
        }
        __syncthreads();
    }
    float4 v = *(const float4*)&X[i];
    if (MODE == 1) {
        float mu = s_mu, sc = s_r;
        v.x = (v.x - mu) * sc; v.y = (v.y - mu) * sc;
        v.z = (v.z - mu) * sc; v.w = (v.w - mu) * sc;
    } else {
        int t0 = (int)(i & (TT - 1));
        float4 m = *(const float4*)&g_tmean[t0];
        float4 r = *(const float4*)&g_trstd[t0];
        v.x = (v.x - m.x) * r.x; v.y = (v.y - m.y) * r.y;
        v.z = (v.z - m.z) * r.z; v.w = (v.w - m.w) * r.w;
    }
    __half2 h0 = __halves2half2(__float2half_rn(v.x), __float2half_rn(v.y));
    __half2 h1 = __halves2half2(__float2half_rn(v.z), __float2half_rn(v.w));
    uint2 w = { *(uint32_t*)&h0, *(uint32_t*)&h1 };
    *(uint2*)&Bt[i] = w;
}

// ---------------- tensor-core GEMM (r9/r13 best config, unchanged) ---------
#define KSTAGE 64
#define NSTG 3
#define A_BYTES 16384
#define STG_BYTES 32768
#define MMA_SMEM (NSTG * STG_BYTES)
#define NKC 8

template <int BETA, int STATS, int TRANS, typename OutT>
__global__ void __launch_bounds__(256, 2)
k_mma(const __half* __restrict__ Wb, const __half* __restrict__ Bt,
      const float* __restrict__ bias, OutT* __restrict__ C, const float* __restrict__ Cin,
      float* __restrict__ bstat) {
    extern __shared__ char dsm[];
    uint32_t smb = smem_u32(dsm);
    int tid = threadIdx.x;
    int wid = tid >> 5, lane = tid & 31;
    int m0 = blockIdx.x * 128, n0 = blockIdx.y * 128;
    int warp_m = wid >> 2, warp_n = wid & 3;

    float acc[4][4][4];
    #pragma unroll
    for (int a = 0; a < 4; a++)
        #pragma unroll
        for (int b = 0; b < 4; b++)
            #pragma unroll
            for (int c = 0; c < 4; c++) acc[a][b][c] = 0.0f;

    int arow = tid >> 3, ach = tid & 7;
    int brow = tid >> 4, bch = tid & 15;

    auto prefetch = [&](int st, int kc) {
        uint32_t sA = smb + st * STG_BYTES;
        uint32_t sB = sA + A_BYTES;
        #pragma unroll
        for (int i = 0; i < 4; i++) {
            int row = arow + i * 32;
            const __half* g = Wb + (size_t)(m0 + row) * 512 + kc * KSTAGE + ach * 8;
            cp_async16(sA + row * 128 + ((ach ^ (row & 7)) << 4), g);
        }
        #pragma unroll
        for (int i = 0; i < 4; i++) {
            int row = brow + i * 16;
            const __half* g = Bt + (size_t)(kc * KSTAGE + row) * NN + n0 + bch * 8;
            cp_async16(sB + row * 256 + ((bch ^ (row & 7)) << 4), g);
        }
    };

    prefetch(0, 0); CP_COMMIT();
    prefetch(1, 1); CP_COMMIT();

    int lr = lane & 7, lq = lane >> 3;
    int rowoff = lr + (lq & 1) * 8;
    int csel = lq >> 1;
    int bk_off = (lq & 1) * 8 + lr;
    int bn_half = lq >> 1;

    for (int i = 0; i < NKC; i++) {
        CP_WAIT1();
        __syncthreads();
        if (i + 2 < NKC) prefetch((i + 2) % NSTG, i + 2);
        CP_COMMIT();

        uint32_t sA = smb + (i % NSTG) * STG_BYTES;
        uint32_t sB = sA + A_BYTES;

        uint32_t bf[2][2][4];
        #pragma unroll
        for (int nf = 0; nf < 2; nf++) {
            int krow = bk_off;
            int nch = warp_n * 4 + nf * 2 + bn_half;
            ldmatrix_x4_trans(bf[0][nf][0], bf[0][nf][1], bf[0][nf][2], bf[0][nf][3],
                              sB + krow * 256 + ((nch ^ (krow & 7)) << 4));
        }
        #pragma unroll
        for (int kk = 0; kk < 4; kk++) {
            int cur = kk & 1;
            if (kk < 3) {
                #pragma unroll
                for (int nf = 0; nf < 2; nf++) {
                    int krow = (kk + 1) * 16 + bk_off;
                    int nch = warp_n * 4 + nf * 2 + bn_half;
                    ldmatrix_x4_trans(bf[cur ^ 1][nf][0], bf[cur ^ 1][nf][1],
                                      bf[cur ^ 1][nf][2], bf[cur ^ 1][nf][3],
                                      sB + krow * 256 + ((nch ^ (krow & 7)) << 4));
                }
            }
            int chnk = kk * 2 + csel;
            uint32_t af[4][4];
            #pragma unroll
            for (int mf = 0; mf < 4; mf++) {
                int row = warp_m * 64 + mf * 16 + rowoff;
                ldmatrix_x4(af[mf][0], af[mf][1], af[mf][2], af[mf][3],
                            sA + row * 128 + ((chnk ^ (row & 7)) << 4));
            }
            #pragma unroll
            for (int mf = 0; mf < 4; mf++)
                #pragma unroll
                for (int t = 0; t < 4; t++)
                    mma16816(acc[mf][t], af[mf],
                             bf[cur][t >> 1][(t & 1) * 2], bf[cur][t >> 1][(t & 1) * 2 + 1]);
        }
    }
    __syncthreads();

    // ---- epilogue ----
    float* colsum = (float*)dsm;
    float* colsq  = colsum + 128;
    float* stg    = (float*)dsm;
    if (STATS == 2) {
        if (tid < 128) { colsum[tid] = 0.0f; colsq[tid] = 0.0f; }
        __syncthreads();
    }
    float s_part = 0.0f, q_part = 0.0f;
    int g = lane >> 2, tg = lane & 3;
    #pragma unroll
    for (int mf = 0; mf < 4; mf++) {
        int mlA = warp_m * 64 + mf * 16 + g;
        int mlB = mlA + 8;
        int mA = m0 + mlA, mB2 = m0 + mlB;
        float bva = bias[mA], bvb = bias[mB2];
        #pragma unroll
        for (int t = 0; t < 4; t++) {
            int nl = warp_n * 32 + t * 8 + tg * 2;
            int n = n0 + nl;
            size_t o0 = (size_t)mA * NN + n;
            size_t o1 = (size_t)mB2 * NN + n;
            float v00 = acc[mf][t][0] + bva, v01 = acc[mf][t][1] + bva;
            float v10 = acc[mf][t][2] + bvb, v11 = acc[mf][t][3] + bvb;
            if (BETA) {
                float2 p0 = *(const float2*)&Cin[o0];
                float2 p1 = *(const float2*)&Cin[o1];
                v00 += p0.x; v01 += p0.y;
                v10 += p1.x; v11 += p1.y;
            }
            if (STATS == 1) {
                s_part += v00 + v01 + v10 + v11;
                q_part += v00 * v00 + v01 * v01 + v10 * v10 + v11 * v11;
            }
            if (STATS == 2) {
                atomicAdd(&colsum[nl], v00 + v10);
                atomicAdd(&colsum[nl + 1], v01 + v11);
                atomicAdd(&colsq[nl], v00 * v00 + v10 * v10);
                atomicAdd(&colsq[nl + 1], v01 * v01 + v11 * v11);
            }
            if (TRANS) {
                stg[nl * 132 + mlA] = v00;
                stg[(nl + 1) * 132 + mlA] = v01;
                stg[nl * 132 + mlB] = v10;
                stg[(nl + 1) * 132 + mlB] = v11;
            } else if (sizeof(OutT) == 4) {
                float2 w0 = { v00, v01 }, w1 = { v10, v11 };
                *(float2*)&((float*)C)[o0] = w0;
                *(float2*)&((float*)C)[o1] = w1;
            } else {
                __half2 h0 = __halves2half2(__float2half_rn(v00), __float2half_rn(v01));
                __half2 h1 = __halves2half2(__float2half_rn(v10), __float2half_rn(v11));
                *(uint32_t*)&((__half*)C)[o0] = *(uint32_t*)&h0;
                *(uint32_t*)&((__half*)C)[o1] = *(uint32_t*)&h1;
            }
        }
    }
    if (STATS == 1) {
        float* red = (float*)dsm;
        red[tid] = s_part; red[256 + tid] = q_part;
        __syncthreads();
        for (int o = 128; o > 0; o >>= 1) {
            if (tid < o) { red[tid] += red[tid + o]; red[256 + tid] += red[256 + tid + o]; }
            __syncthreads();
        }
        if (tid == 0) {
            int b = n0 >> 11;
            atomicAdd(&bstat[2 * b], red[0]);
            atomicAdd(&bstat[2 * b + 1], red[256]);
        }
    }
    if (STATS == 2) {
        __syncthreads();
        if (tid < 128) {
            int t = (n0 + tid) & (TT - 1);
            atomicAdd(&g_tacc[2 * t], colsum[tid]);
            atomicAdd(&g_tacc[2 * t + 1], colsq[tid]);
        }
    }
    if (TRANS) {
        __syncthreads();
        int ml = tid & 127;
        for (int nl = tid >> 7; nl < 128; nl += 2)
            ((float*)C)[(size_t)(n0 + nl) * CC + m0 + ml] = stg[nl * 132 + ml];
    }
}

// ---------------- attention over the batch axis (AT=4, 2 CTAs/SM) ----------
#define AT 4
#define SQ_OFF 0
#define SK_OFF 8192
#define SV_OFF 16384
#define ST_OFF 25600
#define ATTN_SMEM_FLOATS (8192 + 8192 + 9216 + 1056)
#define ATTN_SMEM_BYTES (ATTN_SMEM_FLOATS * 4)

__global__ void __launch_bounds__(256, 2)
k_attn(const __half* __restrict__ QKV, __half* __restrict__ O) {
    extern __shared__ float sm[];
    float* smq = sm + SQ_OFF;   // [4][64][32]
    float* smk = sm + SK_OFF;   // [4][64][32]
    float* smv = sm + SV_OFF;   // [4][64][stride 36]
    float* st  = sm + ST_OFF;   // [32][33]
    int h = blockIdx.y;
    int t0 = blockIdx.x * AT;
    int tid = threadIdx.x;

    const __half* Qh = QKV;
    const __half* Kh = QKV + (size_t)512 * NN;
    const __half* Vh = QKV + (size_t)1024 * NN;

    for (int p0 = tid; p0 < 2048; p0 += 256) {
        int d = p0 >> 5, b = p0 & 31;
        size_t base = ((size_t)(h * 64 + d) * 32 + b) * 2048 + t0;
        uint2 qr = *(const uint2*)&Qh[base];
        uint2 kr = *(const uint2*)&Kh[base];
        uint2 vr = *(const uint2*)&Vh[base];
        __half2* qh = (__half2*)&qr;
        __half2* kh = (__half2*)&kr;
        __half2* vh = (__half2*)&vr;
        #pragma unroll
        for (int j = 0; j < 2; j++) {
            float2 qf = __half22float2(qh[j]);
            float2 kf = __half22float2(kh[j]);
            float2 vf = __half22float2(vh[j]);
            smq[((2 * j) * 64 + d) * 32 + b] = qf.x;
            smq[((2 * j + 1) * 64 + d) * 32 + b] = qf.y;
            smk[((2 * j) * 64 + d) * 32 + b] = kf.x;
            smk[((2 * j + 1) * 64 + d) * 32 + b] = kf.y;
            smv[((2 * j) * 64 + d) * 36 + b] = vf.x;
            smv[((2 * j + 1) * 64 + d) * 36 + b] = vf.y;
        }
    }
    __syncthreads();

    const float scale = 0.125f;
    int sb = tid >> 3, sp0 = (tid & 7) * 4;
    for (int ttk = 0; ttk < AT; ttk++) {
        float a0 = 0, a1 = 0, a2 = 0, a3 = 0;
        #pragma unroll
        for (int d = 0; d < 64; d++) {
            float qv = smq[(ttk * 64 + d) * 32 + sb];
            float4 kv = *(const float4*)&smk[(ttk * 64 + d) * 32 + sp0];
            a0 += qv * kv.x; a1 += qv * kv.y; a2 += qv * kv.z; a3 += qv * kv.w;
        }
        st[sb * 33 + sp0 + 0] = a0 * scale;
        st[sb * 33 + sp0 + 1] = a1 * scale;
        st[sb * 33 + sp0 + 2] = a2 * scale;
        st[sb * 33 + sp0 + 3] = a3 * scale;
        __syncthreads();
        if (tid < 32) {
            const float* row = st + tid * 33;
            float mx = -1e30f;
            #pragma unroll
            for (int j = 0; j < 32; j++) mx = fmaxf(mx, row[j]);
            float ev[32]; float sum = 0.0f;
            #pragma unroll
            for (int j = 0; j < 32; j++) { ev[j] = expf(row[j] - mx); sum += ev[j]; }
            float inv = 1.0f / sum;
            #pragma unroll
            for (int j = 0; j < 32; j++) smq[ttk * 1152 + tid * 36 + j] = ev[j] * inv;
        }
        __syncthreads();
    }

    for (int rep = 0; rep < 8; rep++) {
        int o = tid + rep * 256;
        int ob = o >> 6, od = o & 63;
        float outv[AT];
        #pragma unroll
        for (int s = 0; s < AT; s++) {
            float acc = 0.0f;
            #pragma unroll
            for (int bp = 0; bp < 32; bp += 4) {
                float4 pv = *(const float4*)&smq[s * 1152 + ob * 36 + bp];
                float4 vv = *(const float4*)&smv[(s * 64 + od) * 36 + bp];
                acc += pv.x * vv.x + pv.y * vv.y + pv.z * vv.z + pv.w * vv.w;
            }
            outv[s] = acc;
        }
        size_t base = ((size_t)(h * 64 + od) * 32 + ob) * 2048 + t0;
        __half2 h0 = __halves2half2(__float2half_rn(outv[0]), __float2half_rn(outv[1]));
        __half2 h1 = __halves2half2(__float2half_rn(outv[2]), __float2half_rn(outv[3]));
        uint2 w = { *(uint32_t*)&h0, *(uint32_t*)&h1 };
        *(uint2*)&O[base] = w;
    }
}

// ---------------- launch --------------------------------------------------
extern "C" void kernel_launch(void* const* d_in, const int* in_sizes, int n_in,
                              void* d_out, int out_size) {
    const float* x     = (const float*)d_in[0];
    const float* dw1_w = (const float*)d_in[1];
    const float* dw1_b = (const float*)d_in[2];
    const float* pw1_w = (const float*)d_in[3];
    const float* pw1_b = (const float*)d_in[4];
    const float* dw2_w = (const float*)d_in[5];
    const float* dw2_b = (const float*)d_in[6];
    const float* pw2_w = (const float*)d_in[7];
    const float* pw2_b = (const float*)d_in[8];
    const float* wq = (const float*)d_in[9];
    const float* bq = (const float*)d_in[10];
    const float* wk = (const float*)d_in[11];
    const float* bk = (const float*)d_in[12];
    const float* wv = (const float*)d_in[13];
    const float* bv = (const float*)d_in[14];
    const float* wp = (const float*)d_in[15];
    const float* bp = (const float*)d_in[16];
    const float* ff_w = (const float*)d_in[17];
    const float* ff_b = (const float*)d_in[18];
    float* out = (float*)d_out;

    float *pX, *pBqkv, *pBst;
    __half *pBt, *pQKV, *pWb, *pWb2, *pWp, *pWff, *pWqkv;
    cudaGetSymbolAddress((void**)&pX, gX);
    cudaGetSymbolAddress((void**)&pBt, gBt);
    cudaGetSymbolAddress((void**)&pQKV, gQKV);
    cudaGetSymbolAddress((void**)&pWb, gWb);
    cudaGetSymbolAddress((void**)&pWb2, gWb2);
    cudaGetSymbolAddress((void**)&pWp, gWp);
    cudaGetSymbolAddress((void**)&pWff, gWff);
    cudaGetSymbolAddress((void**)&pWqkv, gWqkv);
    cudaGetSymbolAddress((void**)&pBqkv, gBqkv);
    cudaGetSymbolAddress((void**)&pBst, g_bst);

    cudaFuncSetAttribute(k_attn, cudaFuncAttributeMaxDynamicSharedMemorySize, ATTN_SMEM_BYTES);
    cudaFuncSetAttribute((k_mma<0, 1, 0, float>), cudaFuncAttributeMaxDynamicSharedMemorySize, MMA_SMEM);
    cudaFuncSetAttribute((k_mma<1, 1, 0, float>), cudaFuncAttributeMaxDynamicSharedMemorySize, MMA_SMEM);
    cudaFuncSetAttribute((k_mma<0, 0, 0, __half>), cudaFuncAttributeMaxDynamicSharedMemorySize, MMA_SMEM);
    cudaFuncSetAttribute((k_mma<1, 2, 0, float>), cudaFuncAttributeMaxDynamicSharedMemorySize, MMA_SMEM);
    cudaFuncSetAttribute((k_mma<1, 0, 1, float>), cudaFuncAttributeMaxDynamicSharedMemorySize, MMA_SMEM);

    dim3 mmaG(4, 512);       // m fast -> B tiles shared across m via L2
    dim3 mmaGqkv(12, 512);

    // 0) weight converts + stat zeroing; input transpose + pos-enc (+stats -> stage 0)
    k_cvtall<<<7168, 256>>>(pw1_w, pw2_w, wp, ff_w, wq, wk, wv, bq, bk, bv,
                            pWb, pWb2, pWp, pWff, pWqkv, pBqkv);
    k_transpose_in<<<dim3(TT / 32, CC / 32, BB), dim3(32, 8)>>>(x, pX);

    // 1) conv block 1: X = pw1 @ dwconv1(LN_b(X)) + b   (stats stage 0 -> 1)
    k_dwconv<<<dim3(CC, BB), 256>>>(pX, dw1_w, dw1_b, pBt, pBst);
    k_mma<0, 1, 0, float><<<mmaG, 256, MMA_SMEM>>>(pWb, pBt, pw1_b, pX, pX, pBst + 64);

    // 2) conv blocks 2..4 (shared weights), stats stages 1->2->3->4
    for (int it = 0; it < 3; it++) {
        k_dwconv<<<dim3(CC, BB), 256>>>(pX, dw2_w, dw2_b, pBt, pBst + (it + 1) * 64);
        k_mma<1, 1, 0, float><<<mmaG, 256, MMA_SMEM>>>(pWb2, pBt, pw2_b, pX, pX,
                                                       pBst + (it + 2) * 64);
    }

    // 3) attention over batch axis (merged QKV GEMM, fp16); LN from stage 4
    k_cvtBe<1><<<32768, 256>>>(pX, pBt, pBst + 4 * 64);
    k_mma<0, 0, 0, __half><<<mmaGqkv, 256, MMA_SMEM>>>(pWqkv, pBt, pBqkv, pQKV,
                                                       (const float*)0, (float*)0);
    k_attn<<<dim3(TT / AT, HH), 256, ATTN_SMEM_BYTES>>>(pQKV, pBt);
    k_mma<1, 2, 0, float><<<mmaG, 256, MMA_SMEM>>>(pWp, pBt, bp, pX, pX, (float*)0);
    k_tfinal<<<TT / 256, 256>>>();

    // 4) FF with per-t LN; final GEMM writes output transposed (B,T,F)
    k_cvtBe<2><<<32768, 256>>>(pX, pBt, (const float*)0);
    k_mma<1, 0, 1, float><<<mmaG, 256, MMA_SMEM>>>(pWff, pBt, ff_b, out, pX, (float*)0);

    (void)in_sizes; (void)n_in; (void)out_size;
}

// round 15
// speedup vs baseline: 1.2008x; 1.0394x over previous
#include <cuda_runtime.h>
#include <cuda_fp16.h>
#include <cstdint>
#include <math.h>

// ---------------- problem constants ----------------
#define BB 32
#define TT 2048
#define CC 512          // E == F == 512
#define NN 65536        // B*T
#define HH 8
#define EPS 1e-5
#define INV_BN 9.5367431640625e-7f    // 1/1048576

// ---------------- scratch (device globals; allocation-free rule) ----------
__device__ float gX[33554432];     // state, layout (C, B, T) fp32
__device__ __half gBt[33554432];   // GEMM B operand, K-major [512][65536] fp16
__device__ __half gQKV[100663296]; // merged QKV output fp16 [1536][65536]
__device__ __half gWb[262144];     // pw1 weights fp16
__device__ __half gWb2[262144];    // pw2 weights fp16
__device__ __half gWp[262144];     // wp weights fp16
__device__ __half gWff[262144];    // ff weights fp16
__device__ __half gWqkv[786432];   // merged q|k|v weights fp16 [1536][512]
__device__ float gBqkv[1536];      // merged q|k|v bias

__device__ float g_bst[5 * 64];    // staged per-batch (sum, sumsq): 5 stages x 32 b
__device__ float g_tacc[4096];     // per-t (sum, sumsq)

// ================= helpers =================
__device__ __forceinline__ uint32_t smem_u32(const void* p) {
    uint32_t a;
    asm("{ .reg .u64 t; cvta.to.shared.u64 t, %1; cvt.u32.u64 %0, t; }" : "=r"(a) : "l"(p));
    return a;
}
__device__ __forceinline__ void cp_async16(uint32_t smaddr, const void* g) {
    asm volatile("cp.async.cg.shared.global [%0], [%1], 16;" :: "r"(smaddr), "l"(g));
}
#define CP_COMMIT() asm volatile("cp.async.commit_group;" ::: "memory")
#define CP_WAIT1()  asm volatile("cp.async.wait_group 1;" ::: "memory")

__device__ __forceinline__ void ldmatrix_x4(uint32_t& r0, uint32_t& r1, uint32_t& r2,
                                            uint32_t& r3, uint32_t addr) {
    asm volatile("ldmatrix.sync.aligned.m8n8.x4.shared.b16 {%0,%1,%2,%3}, [%4];"
        : "=r"(r0), "=r"(r1), "=r"(r2), "=r"(r3) : "r"(addr));
}
__device__ __forceinline__ void ldmatrix_x4_trans(uint32_t& r0, uint32_t& r1, uint32_t& r2,
                                                  uint32_t& r3, uint32_t addr) {
    asm volatile("ldmatrix.sync.aligned.m8n8.x4.trans.shared.b16 {%0,%1,%2,%3}, [%4];"
        : "=r"(r0), "=r"(r1), "=r"(r2), "=r"(r3) : "r"(addr));
}
__device__ __forceinline__ void mma16816(float* d, const uint32_t* a, uint32_t b0, uint32_t b1) {
    asm volatile(
        "mma.sync.aligned.m16n8k16.row.col.f32.f16.f16.f32 "
        "{%0,%1,%2,%3}, {%4,%5,%6,%7}, {%8,%9}, {%0,%1,%2,%3};"
        : "+f"(d[0]), "+f"(d[1]), "+f"(d[2]), "+f"(d[3])
        : "r"(a[0]), "r"(a[1]), "r"(a[2]), "r"(a[3]), "r"(b0), "r"(b1));
}

// ---------------- all weight converts + qkv pack + stat zeroing ------------
__global__ void k_cvtall(const float* __restrict__ pw1, const float* __restrict__ pw2,
                         const float* __restrict__ wp, const float* __restrict__ ffw,
                         const float* __restrict__ wq, const float* __restrict__ wk,
                         const float* __restrict__ wv, const float* __restrict__ bq,
                         const float* __restrict__ bk, const float* __restrict__ bv,
                         __half* __restrict__ W1, __half* __restrict__ W2,
                         __half* __restrict__ Wp, __half* __restrict__ Wff,
                         __half* __restrict__ Wqkv, float* __restrict__ Bqkv) {
    int idx = blockIdx.x * 256 + threadIdx.x;
    if (idx < 320) g_bst[idx] = 0.0f;
    if (idx < 4096) g_tacc[idx] = 0.0f;
    if (idx < 262144) {
        W1[idx] = __float2half_rn(pw1[idx]);
    } else if (idx < 524288) {
        int o = idx - 262144; W2[o] = __float2half_rn(pw2[o]);
    } else if (idx < 786432) {
        int o = idx - 524288; Wp[o] = __float2half_rn(wp[o]);
    } else if (idx < 1048576) {
        int o = idx - 786432; Wff[o] = __float2half_rn(ffw[o]);
    } else {
        int o2 = idx - 1048576;           // 0..786431
        int sel = o2 >> 18;
        int off = o2 & 262143;
        const float* src = (sel == 0) ? wq : ((sel == 1) ? wk : wv);
        Wqkv[o2] = __float2half_rn(src[off]);
        if (off < 512) {
            const float* bs = (sel == 0) ? bq : ((sel == 1) ? bk : bv);
            Bqkv[sel * 512 + off] = bs[off];
        }
    }
}

// ---------------- input transpose + positional encoding + batch stats ------
__global__ void k_transpose_in(const float* __restrict__ in, float* __restrict__ X) {
    __shared__ float tile[32][33];
    __shared__ float rs[256], rq[256];
    int b = blockIdx.z;
    int t0 = blockIdx.x * 32, c0 = blockIdx.y * 32;
    int tx = threadIdx.x, ty = threadIdx.y;
    #pragma unroll
    for (int i = ty; i < 32; i += 8)
        tile[i][tx] = in[((size_t)b * TT + t0 + i) * CC + c0 + tx];
    __syncthreads();
    float s = 0.0f, q = 0.0f;
    #pragma unroll
    for (int i = ty; i < 32; i += 8) {
        int c = c0 + i;
        float div = expf((float)(c & ~1) * (-9.210340371976184f / 512.0f));
        float ang = (float)b * div;
        float pe = (c & 1) ? cosf(ang) : sinf(ang);
        float v = tile[tx][i] + pe;
        X[((size_t)c * BB + b) * TT + t0 + tx] = v;
        s += v; q += v * v;
    }
    int tid = ty * 32 + tx;
    rs[tid] = s; rq[tid] = q;
    __syncthreads();
    for (int o = 128; o > 0; o >>= 1) {
        if (tid < o) { rs[tid] += rs[tid + o]; rq[tid] += rq[tid + o]; }
        __syncthreads();
    }
    if (tid == 0) {
        atomicAdd(&g_bst[2 * b], rs[0]);
        atomicAdd(&g_bst[2 * b + 1], rq[0]);
    }
}

// ---------------- fused per-batch-LN + depthwise conv (k=7) -> fp16 --------
__global__ void k_dwconv(const float* __restrict__ X, const float* __restrict__ dww,
                         const float* __restrict__ dwb, __half* __restrict__ D,
                         const float* __restrict__ bst) {
    int c = blockIdx.x, b = blockIdx.y;
    int tid = threadIdx.x;
    __shared__ float s[TT + 16];   // x[t] at s[t+4]
    __shared__ float s_mu, s_r;
    const float4* row4 = (const float4*)(X + ((size_t)c * BB + b) * TT);
    float4 v0 = row4[tid];
    float4 v1 = row4[tid + 256];
    if (tid == 0) {
        float sum = bst[2 * b], sq = bst[2 * b + 1];
        float mu = sum * INV_BN;
        float var = sq * INV_BN - mu * mu;
        s_mu = mu;
        s_r = rsqrtf(var + (float)EPS);
    }
    __syncthreads();
    float mu = s_mu, r = s_r;
    v0.x = (v0.x - mu) * r; v0.y = (v0.y - mu) * r;
    v0.z = (v0.z - mu) * r; v0.w = (v0.w - mu) * r;
    v1.x = (v1.x - mu) * r; v1.y = (v1.y - mu) * r;
    v1.z = (v1.z - mu) * r; v1.w = (v1.w - mu) * r;
    *(float4*)&s[4 + tid * 4] = v0;
    *(float4*)&s[4 + (tid + 256) * 4] = v1;
    if (tid < 4) s[tid] = 0.0f;
    else if (tid < 8) s[2048 + tid] = 0.0f;
    __syncthreads();
    float w0 = dww[c * 7 + 0], w1 = dww[c * 7 + 1], w2 = dww[c * 7 + 2], w3 = dww[c * 7 + 3];
    float w4 = dww[c * 7 + 4], w5 = dww[c * 7 + 5], w6 = dww[c * 7 + 6];
    float bias = dwb[c];
    int t0 = tid * 8;
    float xv[16];
    *(float4*)&xv[0]  = *(const float4*)&s[t0];
    *(float4*)&xv[4]  = *(const float4*)&s[t0 + 4];
    *(float4*)&xv[8]  = *(const float4*)&s[t0 + 8];
    *(float4*)&xv[12] = *(const float4*)&s[t0 + 12];
    __half2 oh[4];
    #pragma unroll
    for (int j = 0; j < 8; j += 2) {
        float a0 = bias, a1 = bias;
        a0 += w0 * xv[j + 1]; a1 += w0 * xv[j + 2];
        a0 += w1 * xv[j + 2]; a1 += w1 * xv[j + 3];
        a0 += w2 * xv[j + 3]; a1 += w2 * xv[j + 4];
        a0 += w3 * xv[j + 4]; a1 += w3 * xv[j + 5];
        a0 += w4 * xv[j + 5]; a1 += w4 * xv[j + 6];
        a0 += w5 * xv[j + 6]; a1 += w5 * xv[j + 7];
        a0 += w6 * xv[j + 7]; a1 += w6 * xv[j + 8];
        oh[j >> 1] = __halves2half2(__float2half_rn(a0), __float2half_rn(a1));
    }
    uint4 wv = { *(uint32_t*)&oh[0], *(uint32_t*)&oh[1], *(uint32_t*)&oh[2], *(uint32_t*)&oh[3] };
    *(uint4*)(D + ((size_t)c * BB + b) * TT + t0) = wv;
}

// ---------------- elementwise LN + fp32->fp16 (layout preserved) -----------
// MODE 1: per-batch (inline finalize, one b per block)
// MODE 2: per-t (inline finalize from g_tacc, per thread — replaces k_tfinal)
template <int MODE>
__global__ void k_cvtBe(const float* __restrict__ X, __half* __restrict__ Bt,
                        const float* __restrict__ bst) {
    __shared__ float s_mu, s_r;
    size_t i = ((size_t)blockIdx.x * 256 + threadIdx.x) * 4;
    if (MODE == 1) {
        if (threadIdx.x == 0) {
            int b = (int)((i >> 11) & 31);
            float sum = bst[2 * b], sq = bst[2 * b + 1];
            float mu = sum * INV_BN;
            float var = sq * INV_BN - mu * mu;
            s_mu = mu;
            s_r = rsqrtf(var + (float)EPS);
        }
        __syncthreads();
    }
    float4 v = *(const float4*)&X[i];
    if (MODE == 1) {
        float mu = s_mu, sc = s_r;
        v.x = (v.x - mu) * sc; v.y = (v.y - mu) * sc;
        v.z = (v.z - mu) * sc; v.w = (v.w - mu) * sc;
    } else {
        int t0 = (int)(i & (TT - 1));
        float4 a0 = *(const float4*)&g_tacc[2 * t0];       // (s0,q0,s1,q1)
        float4 a1 = *(const float4*)&g_tacc[2 * t0 + 4];   // (s2,q2,s3,q3)
        float mu0 = a0.x * (1.0f / 16384.0f), mu1 = a0.z * (1.0f / 16384.0f);
        float mu2 = a1.x * (1.0f / 16384.0f), mu3 = a1.z * (1.0f / 16384.0f);
        float r0 = rsqrtf(a0.y * (1.0f / 16384.0f) - mu0 * mu0 + (float)EPS);
        float r1 = rsqrtf(a0.w * (1.0f / 16384.0f) - mu1 * mu1 + (float)EPS);
        float r2 = rsqrtf(a1.y * (1.0f / 16384.0f) - mu2 * mu2 + (float)EPS);
        float r3 = rsqrtf(a1.w * (1.0f / 16384.0f) - mu3 * mu3 + (float)EPS);
        v.x = (v.x - mu0) * r0; v.y = (v.y - mu1) * r1;
        v.z = (v.z - mu2) * r2; v.w = (v.w - mu3) * r3;
    }
    __half2 h0 = __halves2half2(__float2half_rn(v.x), __float2half_rn(v.y));
    __half2 h1 = __halves2half2(__float2half_rn(v.z), __float2half_rn(v.w));
    uint2 w = { *(uint32_t*)&h0, *(uint32_t*)&h1 };
    *(uint2*)&Bt[i] = w;
}

// ---------------- tensor-core GEMM: C[M,65536] (+)= W @ X + bias ------------
// A fp16 [M][512] row-major; B fp16 [512][65536] K-major.
// CTA 64x128, 8 warps (2x4, warp tile 32x32), K chunks of 64, 3-stage cp.async,
// 3 CTAs/SM (24 warps). STATS: 0/1/2, TRANS: (n,m) output.
#define KSTAGE 64
#define NSTG 3
#define A_BYTES 8192                   // 64 m-rows x 128 B
#define STG_BYTES 24576                // A(8KB) + B(16KB: 64 k-rows x 256 B)
#define MMA_SMEM (NSTG * STG_BYTES)    // 73728
#define NKC 8

template <int BETA, int STATS, int TRANS, typename OutT>
__global__ void __launch_bounds__(256, 3)
k_mma(const __half* __restrict__ Wb, const __half* __restrict__ Bt,
      const float* __restrict__ bias, OutT* __restrict__ C, const float* __restrict__ Cin,
      float* __restrict__ bstat) {
    extern __shared__ char dsm[];
    uint32_t smb = smem_u32(dsm);
    int tid = threadIdx.x;
    int wid = tid >> 5, lane = tid & 31;
    int m0 = blockIdx.x * 64, n0 = blockIdx.y * 128;
    int warp_m = wid >> 2, warp_n = wid & 3;   // 2 x 4 warps, warp tile 32x32

    float acc[2][4][4];
    #pragma unroll
    for (int a = 0; a < 2; a++)
        #pragma unroll
        for (int b = 0; b < 4; b++)
            #pragma unroll
            for (int c = 0; c < 4; c++) acc[a][b][c] = 0.0f;

    int arow = tid >> 3, ach = tid & 7;    // A: 32 rows x 8 chunks per pass (2 passes)
    int brow = tid >> 4, bch = tid & 15;   // B: 16 rows x 16 chunks per pass (4 passes)

    auto prefetch = [&](int st, int kc) {
        uint32_t sA = smb + st * STG_BYTES;
        uint32_t sB = sA + A_BYTES;
        #pragma unroll
        for (int i = 0; i < 2; i++) {
            int row = arow + i * 32;
            const __half* g = Wb + (size_t)(m0 + row) * 512 + kc * KSTAGE + ach * 8;
            cp_async16(sA + row * 128 + ((ach ^ (row & 7)) << 4), g);
        }
        #pragma unroll
        for (int i = 0; i < 4; i++) {
            int row = brow + i * 16;
            const __half* g = Bt + (size_t)(kc * KSTAGE + row) * NN + n0 + bch * 8;
            cp_async16(sB + row * 256 + ((bch ^ (row & 7)) << 4), g);
        }
    };

    prefetch(0, 0); CP_COMMIT();
    prefetch(1, 1); CP_COMMIT();

    int lr = lane & 7, lq = lane >> 3;
    int rowoff = lr + (lq & 1) * 8;
    int csel = lq >> 1;
    int bk_off = (lq & 1) * 8 + lr;
    int bn_half = lq >> 1;

    for (int i = 0; i < NKC; i++) {
        CP_WAIT1();
        __syncthreads();
        if (i + 2 < NKC) prefetch((i + 2) % NSTG, i + 2);
        CP_COMMIT();

        uint32_t sA = smb + (i % NSTG) * STG_BYTES;
        uint32_t sB = sA + A_BYTES;

        uint32_t bf[2][2][4];
        #pragma unroll
        for (int nf = 0; nf < 2; nf++) {
            int krow = bk_off;
            int nch = warp_n * 4 + nf * 2 + bn_half;
            ldmatrix_x4_trans(bf[0][nf][0], bf[0][nf][1], bf[0][nf][2], bf[0][nf][3],
                              sB + krow * 256 + ((nch ^ (krow & 7)) << 4));
        }
        #pragma unroll
        for (int kk = 0; kk < 4; kk++) {
            int cur = kk & 1;
            if (kk < 3) {
                #pragma unroll
                for (int nf = 0; nf < 2; nf++) {
                    int krow = (kk + 1) * 16 + bk_off;
                    int nch = warp_n * 4 + nf * 2 + bn_half;
                    ldmatrix_x4_trans(bf[cur ^ 1][nf][0], bf[cur ^ 1][nf][1],
                                      bf[cur ^ 1][nf][2], bf[cur ^ 1][nf][3],
                                      sB + krow * 256 + ((nch ^ (krow & 7)) << 4));
                }
            }
            int chnk = kk * 2 + csel;
            uint32_t af[2][4];
            #pragma unroll
            for (int mf = 0; mf < 2; mf++) {
                int row = warp_m * 32 + mf * 16 + rowoff;
                ldmatrix_x4(af[mf][0], af[mf][1], af[mf][2], af[mf][3],
                            sA + row * 128 + ((chnk ^ (row & 7)) << 4));
            }
            #pragma unroll
            for (int mf = 0; mf < 2; mf++)
                #pragma unroll
                for (int t = 0; t < 4; t++)
                    mma16816(acc[mf][t], af[mf],
                             bf[cur][t >> 1][(t & 1) * 2], bf[cur][t >> 1][(t & 1) * 2 + 1]);
        }
    }
    __syncthreads();

    // ---- epilogue ----
    float* colsum = (float*)dsm;        // STATS==2: [128] + [128]
    float* colsq  = colsum + 128;
    float* stg    = (float*)dsm;        // TRANS: [128][68]
    if (STATS == 2) {
        if (tid < 128) { colsum[tid] = 0.0f; colsq[tid] = 0.0f; }
        __syncthreads();
    }
    float s_part = 0.0f, q_part = 0.0f;
    int g = lane >> 2, tg = lane & 3;
    #pragma unroll
    for (int mf = 0; mf < 2; mf++) {
        int mlA = warp_m * 32 + mf * 16 + g;
        int mlB = mlA + 8;
        int mA = m0 + mlA, mB2 = m0 + mlB;
        float bva = bias[mA], bvb = bias[mB2];
        #pragma unroll
        for (int t = 0; t < 4; t++) {
            int nl = warp_n * 32 + t * 8 + tg * 2;
            int n = n0 + nl;
            size_t o0 = (size_t)mA * NN + n;
            size_t o1 = (size_t)mB2 * NN + n;
            float v00 = acc[mf][t][0] + bva, v01 = acc[mf][t][1] + bva;
            float v10 = acc[mf][t][2] + bvb, v11 = acc[mf][t][3] + bvb;
            if (BETA) {
                float2 p0 = *(const float2*)&Cin[o0];
                float2 p1 = *(const float2*)&Cin[o1];
                v00 += p0.x; v01 += p0.y;
                v10 += p1.x; v11 += p1.y;
            }
            if (STATS == 1) {
                s_part += v00 + v01 + v10 + v11;
                q_part += v00 * v00 + v01 * v01 + v10 * v10 + v11 * v11;
            }
            if (STATS == 2) {
                atomicAdd(&colsum[nl], v00 + v10);
                atomicAdd(&colsum[nl + 1], v01 + v11);
                atomicAdd(&colsq[nl], v00 * v00 + v10 * v10);
                atomicAdd(&colsq[nl + 1], v01 * v01 + v11 * v11);
            }
            if (TRANS) {
                stg[nl * 68 + mlA] = v00;
                stg[(nl + 1) * 68 + mlA] = v01;
                stg[nl * 68 + mlB] = v10;
                stg[(nl + 1) * 68 + mlB] = v11;
            } else if (sizeof(OutT) == 4) {
                float2 w0 = { v00, v01 }, w1 = { v10, v11 };
                *(float2*)&((float*)C)[o0] = w0;
                *(float2*)&((float*)C)[o1] = w1;
            } else {
                __half2 h0 = __halves2half2(__float2half_rn(v00), __float2half_rn(v01));
                __half2 h1 = __halves2half2(__float2half_rn(v10), __float2half_rn(v11));
                *(uint32_t*)&((__half*)C)[o0] = *(uint32_t*)&h0;
                *(uint32_t*)&((__half*)C)[o1] = *(uint32_t*)&h1;
            }
        }
    }
    if (STATS == 1) {
        float* red = (float*)dsm;
        red[tid] = s_part; red[256 + tid] = q_part;
        __syncthreads();
        for (int o = 128; o > 0; o >>= 1) {
            if (tid < o) { red[tid] += red[tid + o]; red[256 + tid] += red[256 + tid + o]; }
            __syncthreads();
        }
        if (tid == 0) {
            int b = n0 >> 11;
            atomicAdd(&bstat[2 * b], red[0]);
            atomicAdd(&bstat[2 * b + 1], red[256]);
        }
    }
    if (STATS == 2) {
        __syncthreads();
        if (tid < 128) {
            int t = (n0 + tid) & (TT - 1);
            atomicAdd(&g_tacc[2 * t], colsum[tid]);
            atomicAdd(&g_tacc[2 * t + 1], colsq[tid]);
        }
    }
    if (TRANS) {
        __syncthreads();
        int ml = tid & 63;
        for (int nl = tid >> 6; nl < 128; nl += 4)
            ((float*)C)[(size_t)(n0 + nl) * CC + m0 + ml] = stg[nl * 68 + ml];
    }
}

// ---------------- attention over the batch axis (AT=4, 2 CTAs/SM) ----------
#define AT 4
#define SQ_OFF 0
#define SK_OFF 8192
#define SV_OFF 16384
#define ST_OFF 25600
#define ATTN_SMEM_FLOATS (8192 + 8192 + 9216 + 1056)
#define ATTN_SMEM_BYTES (ATTN_SMEM_FLOATS * 4)

__global__ void __launch_bounds__(256, 2)
k_attn(const __half* __restrict__ QKV, __half* __restrict__ O) {
    extern __shared__ float sm[];
    float* smq = sm + SQ_OFF;
    float* smk = sm + SK_OFF;
    float* smv = sm + SV_OFF;
    float* st  = sm + ST_OFF;
    int h = blockIdx.y;
    int t0 = blockIdx.x * AT;
    int tid = threadIdx.x;

    const __half* Qh = QKV;
    const __half* Kh = QKV + (size_t)512 * NN;
    const __half* Vh = QKV + (size_t)1024 * NN;

    for (int p0 = tid; p0 < 2048; p0 += 256) {
        int d = p0 >> 5, b = p0 & 31;
        size_t base = ((size_t)(h * 64 + d) * 32 + b) * 2048 + t0;
        uint2 qr = *(const uint2*)&Qh[base];
        uint2 kr = *(const uint2*)&Kh[base];
        uint2 vr = *(const uint2*)&Vh[base];
        __half2* qh = (__half2*)&qr;
        __half2* kh = (__half2*)&kr;
        __half2* vh = (__half2*)&vr;
        #pragma unroll
        for (int j = 0; j < 2; j++) {
            float2 qf = __half22float2(qh[j]);
            float2 kf = __half22float2(kh[j]);
            float2 vf = __half22float2(vh[j]);
            smq[((2 * j) * 64 + d) * 32 + b] = qf.x;
            smq[((2 * j + 1) * 64 + d) * 32 + b] = qf.y;
            smk[((2 * j) * 64 + d) * 32 + b] = kf.x;
            smk[((2 * j + 1) * 64 + d) * 32 + b] = kf.y;
            smv[((2 * j) * 64 + d) * 36 + b] = vf.x;
            smv[((2 * j + 1) * 64 + d) * 36 + b] = vf.y;
        }
    }
    __syncthreads();

    const float scale = 0.125f;
    int sb = tid >> 3, sp0 = (tid & 7) * 4;
    for (int ttk = 0; ttk < AT; ttk++) {
        float a0 = 0, a1 = 0, a2 = 0, a3 = 0;
        #pragma unroll
        for (int d = 0; d < 64; d++) {
            float qv = smq[(ttk * 64 + d) * 32 + sb];
            float4 kv = *(const float4*)&smk[(ttk * 64 + d) * 32 + sp0];
            a0 += qv * kv.x; a1 += qv * kv.y; a2 += qv * kv.z; a3 += qv * kv.w;
        }
        st[sb * 33 + sp0 + 0] = a0 * scale;
        st[sb * 33 + sp0 + 1] = a1 * scale;
        st[sb * 33 + sp0 + 2] = a2 * scale;
        st[sb * 33 + sp0 + 3] = a3 * scale;
        __syncthreads();
        if (tid < 32) {
            const float* row = st + tid * 33;
            float mx = -1e30f;
            #pragma unroll
            for (int j = 0; j < 32; j++) mx = fmaxf(mx, row[j]);
            float ev[32]; float sum = 0.0f;
            #pragma unroll
            for (int j = 0; j < 32; j++) { ev[j] = expf(row[j] - mx); sum += ev[j]; }
            float inv = 1.0f / sum;
            #pragma unroll
            for (int j = 0; j < 32; j++) smq[ttk * 1152 + tid * 36 + j] = ev[j] * inv;
        }
        __syncthreads();
    }

    for (int rep = 0; rep < 8; rep++) {
        int o = tid + rep * 256;
        int ob = o >> 6, od = o & 63;
        float outv[AT];
        #pragma unroll
        for (int s = 0; s < AT; s++) {
            float acc = 0.0f;
            #pragma unroll
            for (int bp = 0; bp < 32; bp += 4) {
                float4 pv = *(const float4*)&smq[s * 1152 + ob * 36 + bp];
                float4 vv = *(const float4*)&smv[(s * 64 + od) * 36 + bp];
                acc += pv.x * vv.x + pv.y * vv.y + pv.z * vv.z + pv.w * vv.w;
            }
            outv[s] = acc;
        }
        size_t base = ((size_t)(h * 64 + od) * 32 + ob) * 2048 + t0;
        __half2 h0 = __halves2half2(__float2half_rn(outv[0]), __float2half_rn(outv[1]));
        __half2 h1 = __halves2half2(__float2half_rn(outv[2]), __float2half_rn(outv[3]));
        uint2 w = { *(uint32_t*)&h0, *(uint32_t*)&h1 };
        *(uint2*)&O[base] = w;
    }
}

// ---------------- launch --------------------------------------------------
extern "C" void kernel_launch(void* const* d_in, const int* in_sizes, int n_in,
                              void* d_out, int out_size) {
    const float* x     = (const float*)d_in[0];
    const float* dw1_w = (const float*)d_in[1];
    const float* dw1_b = (const float*)d_in[2];
    const float* pw1_w = (const float*)d_in[3];
    const float* pw1_b = (const float*)d_in[4];
    const float* dw2_w = (const float*)d_in[5];
    const float* dw2_b = (const float*)d_in[6];
    const float* pw2_w = (const float*)d_in[7];
    const float* pw2_b = (const float*)d_in[8];
    const float* wq = (const float*)d_in[9];
    const float* bq = (const float*)d_in[10];
    const float* wk = (const float*)d_in[11];
    const float* bk = (const float*)d_in[12];
    const float* wv = (const float*)d_in[13];
    const float* bv = (const float*)d_in[14];
    const float* wp = (const float*)d_in[15];
    const float* bp = (const float*)d_in[16];
    const float* ff_w = (const float*)d_in[17];
    const float* ff_b = (const float*)d_in[18];
    float* out = (float*)d_out;

    float *pX, *pBqkv, *pBst;
    __half *pBt, *pQKV, *pWb, *pWb2, *pWp, *pWff, *pWqkv;
    cudaGetSymbolAddress((void**)&pX, gX);
    cudaGetSymbolAddress((void**)&pBt, gBt);
    cudaGetSymbolAddress((void**)&pQKV, gQKV);
    cudaGetSymbolAddress((void**)&pWb, gWb);
    cudaGetSymbolAddress((void**)&pWb2, gWb2);
    cudaGetSymbolAddress((void**)&pWp, gWp);
    cudaGetSymbolAddress((void**)&pWff, gWff);
    cudaGetSymbolAddress((void**)&pWqkv, gWqkv);
    cudaGetSymbolAddress((void**)&pBqkv, gBqkv);
    cudaGetSymbolAddress((void**)&pBst, g_bst);

    cudaFuncSetAttribute(k_attn, cudaFuncAttributeMaxDynamicSharedMemorySize, ATTN_SMEM_BYTES);
    cudaFuncSetAttribute((k_mma<0, 1, 0, float>), cudaFuncAttributeMaxDynamicSharedMemorySize, MMA_SMEM);
    cudaFuncSetAttribute((k_mma<1, 1, 0, float>), cudaFuncAttributeMaxDynamicSharedMemorySize, MMA_SMEM);
    cudaFuncSetAttribute((k_mma<0, 0, 0, __half>), cudaFuncAttributeMaxDynamicSharedMemorySize, MMA_SMEM);
    cudaFuncSetAttribute((k_mma<1, 2, 0, float>), cudaFuncAttributeMaxDynamicSharedMemorySize, MMA_SMEM);
    cudaFuncSetAttribute((k_mma<1, 0, 1, float>), cudaFuncAttributeMaxDynamicSharedMemorySize, MMA_SMEM);

    dim3 mmaG(8, 512);       // m fast -> B tiles shared across m via L2
    dim3 mmaGqkv(24, 512);

    // 0) weight converts + stat zeroing; input transpose + pos-enc (+stats -> stage 0)
    k_cvtall<<<7168, 256>>>(pw1_w, pw2_w, wp, ff_w, wq, wk, wv, bq, bk, bv,
                            pWb, pWb2, pWp, pWff, pWqkv, pBqkv);
    k_transpose_in<<<dim3(TT / 32, CC / 32, BB), dim3(32, 8)>>>(x, pX);

    // 1) conv block 1: X = pw1 @ dwconv1(LN_b(X)) + b   (stats stage 0 -> 1)
    k_dwconv<<<dim3(CC, BB), 256>>>(pX, dw1_w, dw1_b, pBt, pBst);
    k_mma<0, 1, 0, float><<<mmaG, 256, MMA_SMEM>>>(pWb, pBt, pw1_b, pX, pX, pBst + 64);

    // 2) conv blocks 2..4 (shared weights), stats stages 1->2->3->4
    for (int it = 0; it < 3; it++) {
        k_dwconv<<<dim3(CC, BB), 256>>>(pX, dw2_w, dw2_b, pBt, pBst + (it + 1) * 64);
        k_mma<1, 1, 0, float><<<mmaG, 256, MMA_SMEM>>>(pWb2, pBt, pw2_b, pX, pX,
                                                       pBst + (it + 2) * 64);
    }

    // 3) attention over batch axis (merged QKV GEMM, fp16); LN from stage 4
    k_cvtBe<1><<<32768, 256>>>(pX, pBt, pBst + 4 * 64);
    k_mma<0, 0, 0, __half><<<mmaGqkv, 256, MMA_SMEM>>>(pWqkv, pBt, pBqkv, pQKV,
                                                       (const float*)0, (float*)0);
    k_attn<<<dim3(TT / AT, HH), 256, ATTN_SMEM_BYTES>>>(pQKV, pBt);
    k_mma<1, 2, 0, float><<<mmaG, 256, MMA_SMEM>>>(pWp, pBt, bp, pX, pX, (float*)0);

    // 4) FF with per-t LN (inline finalize); final GEMM writes output (B,T,F)
    k_cvtBe<2><<<32768, 256>>>(pX, pBt, (const float*)0);
    k_mma<1, 0, 1, float><<<mmaG, 256, MMA_SMEM>>>(pWff, pBt, ff_b, out, pX, (float*)0);

    (void)in_sizes; (void)n_in; (void)out_size;
}